// round 8
// baseline (speedup 1.0000x reference)
#include <cuda_runtime.h>
#include <cuda_bf16.h>
#include <cstdint>
#include <cstddef>

#define TT   2048
#define BB   16
#define DIMK 1024
#define NN   64
#define NTOT 256
#define MROWS (TT*BB)
#define CHUNK 16
#define CH19  (CHUNK+3)
#define NCH   (TT/CHUNK)

// Does this compilation pass support tcgen05 (arch-specific sm_100a/sm_103a)?
#if defined(__CUDA_ARCH__) && (__CUDA_ARCH__ >= 1000) && \
    (defined(__CUDA_ARCH_FEAT_SM103_ALL) || defined(__CUDA_ARCH_FEAT_SM100_ALL))
#define HAS_TC 1
#else
#define HAS_TC 0
#endif

// ---------------- device scratch ----------------
__device__ __align__(128) __nv_bfloat16 g_xhi[(size_t)MROWS * DIMK];
__device__ __align__(128) __nv_bfloat16 g_xlo[(size_t)MROWS * DIMK];
__device__ __align__(128) __nv_bfloat16 g_whi[NTOT * DIMK];
__device__ __align__(128) __nv_bfloat16 g_wlo[NTOT * DIMK];
__device__ __align__(128) float scr_w[NTOT * DIMK];   // packed fp32 weights (fallback path)
// per row m=(t*B+b): [kn(64)|v(64)|q(64)|g(64)]; +4 timesteps of zero pad (never written)
__device__ __align__(128) float scr_raw[(size_t)(MROWS + 4 * BB) * NTOT];
// per row m: [P1,R1,P2,R2,P3,R3,c,0]  (P_j = kn_t.kn_{t+j}, R_j = kn_t.q_{t+j}, c = kn_t.q_t)
__device__ __align__(128) float scr_pr[(size_t)MROWS * 8];

// ---------------- helpers ----------------
#define SWZ(off) ((off) ^ (((off) >> 3) & 0x70))

__device__ __forceinline__ void cp_async16(void *smem_dst, const void *gsrc) {
    unsigned sa = (unsigned)__cvta_generic_to_shared(smem_dst);
    asm volatile("cp.async.ca.shared.global [%0], [%1], 16;" :: "r"(sa), "l"(gsrc));
}

// f32x2 helpers (fallback GEMM)
__device__ __forceinline__ unsigned long long pack2(float x, float y) {
    unsigned long long r;
    asm("mov.b64 %0, {%1, %2};" : "=l"(r) : "f"(x), "f"(y));
    return r;
}
__device__ __forceinline__ void unpack2(unsigned long long v, float &x, float &y) {
    asm("mov.b64 {%0, %1}, %2;" : "=f"(x), "=f"(y) : "l"(v));
}
__device__ __forceinline__ void ffma2(unsigned long long &c, unsigned long long a, unsigned long long b) {
    asm("fma.rn.f32x2 %0, %1, %2, %0;" : "+l"(c) : "l"(a), "l"(b));
}

// split fp32 -> (hi, lo) bf16
__device__ __forceinline__ void split4(float4 v, uint2 &uh, uint2 &ul) {
    __nv_bfloat16 h0 = __float2bfloat16(v.x), h1 = __float2bfloat16(v.y);
    __nv_bfloat16 h2 = __float2bfloat16(v.z), h3 = __float2bfloat16(v.w);
    __nv_bfloat16 l0 = __float2bfloat16(v.x - __bfloat162float(h0));
    __nv_bfloat16 l1 = __float2bfloat16(v.y - __bfloat162float(h1));
    __nv_bfloat16 l2 = __float2bfloat16(v.z - __bfloat162float(h2));
    __nv_bfloat16 l3 = __float2bfloat16(v.w - __bfloat162float(h3));
    uh.x = ((uint32_t)__bfloat16_as_ushort(h1) << 16) | __bfloat16_as_ushort(h0);
    uh.y = ((uint32_t)__bfloat16_as_ushort(h3) << 16) | __bfloat16_as_ushort(h2);
    ul.x = ((uint32_t)__bfloat16_as_ushort(l1) << 16) | __bfloat16_as_ushort(l0);
    ul.y = ((uint32_t)__bfloat16_as_ushort(l3) << 16) | __bfloat16_as_ushort(l2);
}

#if HAS_TC
__device__ __forceinline__ uint64_t make_desc(uint32_t a) {
    return ((uint64_t)2 << 61) | ((uint64_t)1 << 46) | ((uint64_t)64 << 32) |
           ((uint64_t)1 << 16) | ((a >> 4) & 0x3FFF);
}
__device__ __forceinline__ void mbar_init(uint32_t addr, uint32_t cnt) {
    asm volatile("mbarrier.init.shared.b64 [%0], %1;" :: "r"(addr), "r"(cnt) : "memory");
}
__device__ __forceinline__ void mbar_wait(uint32_t addr, uint32_t parity) {
    uint32_t done;
    asm volatile(
        "{\n\t.reg .pred p;\n\t"
        "mbarrier.try_wait.parity.acquire.cta.shared::cta.b64 p, [%1], %2;\n\t"
        "selp.b32 %0, 1, 0, p;\n\t}"
        : "=r"(done) : "r"(addr), "r"(parity) : "memory");
    if (!done) {
        asm volatile(
            "{\n\t.reg .pred P1;\n\t"
            "WL_%=:\n\t"
            "mbarrier.try_wait.parity.acquire.cta.shared::cta.b64 P1, [%0], %1, 0x989680;\n\t"
            "@P1 bra.uni WD_%=;\n\t"
            "bra.uni WL_%=;\n\t"
            "WD_%=:\n\t}"
            :: "r"(addr), "r"(parity) : "memory");
    }
}
__device__ __forceinline__ void mma_f16_ss(uint32_t d, uint64_t a, uint64_t b,
                                           uint32_t idesc, uint32_t en) {
    asm volatile(
        "{\n\t.reg .pred p;\n\t"
        "setp.ne.u32 p, %5, 0;\n\t"
        "tcgen05.mma.cta_group::1.kind::f16 [%0], %1, %2, %3, {%4, %4, %4, %4}, p;\n\t}"
        :: "r"(d), "l"(a), "l"(b), "r"(idesc), "r"(0u), "r"(en) : "memory");
}
#endif

// ======================================================================
// Weight / activation prep kernels (each a no-op in the pass that
// doesn't need it)
// ======================================================================
__global__ void copyw_kernel(const float *__restrict__ wk, const float *__restrict__ wv,
                             const float *__restrict__ wq, const float *__restrict__ wb) {
#if !HAS_TC
    int i = blockIdx.x * 256 + threadIdx.x;
    int sel = i >> 16, off = i & 65535;
    const float *src = (sel == 0) ? wk : (sel == 1) ? wv : (sel == 2) ? wq : wb;
    scr_w[i] = src[off];
#endif
}

__global__ void convw_kernel(const float *__restrict__ wk, const float *__restrict__ wv,
                             const float *__restrict__ wq, const float *__restrict__ wb) {
#if HAS_TC
    int g = blockIdx.x * 256 + threadIdx.x;
    int i4 = g * 4;
    int n = i4 >> 10, k = i4 & 1023;
    int sel = n >> 6, r = n & 63;
    const float *src = (sel == 0) ? wk : (sel == 1) ? wv : (sel == 2) ? wq : wb;
    float4 v = *(const float4 *)(src + (size_t)r * DIMK + k);
    uint2 uh, ul;
    split4(v, uh, ul);
    *(uint2 *)(g_whi + i4) = uh;
    *(uint2 *)(g_wlo + i4) = ul;
#endif
}

__global__ void convx_kernel(const float *__restrict__ x) {
#if HAS_TC
    size_t i4 = ((size_t)blockIdx.x * 256 + threadIdx.x) * 4;
    float4 v = *(const float4 *)(x + i4);
    uint2 uh, ul;
    split4(v, uh, ul);
    *(uint2 *)(g_xhi + i4) = uh;
    *(uint2 *)(g_xlo + i4) = ul;
#endif
}

// ======================================================================
// Fallback fp32 GEMM (body only in non-tcgen05 passes)
// ======================================================================
__global__ __launch_bounds__(256, 2) void fb_gemm_kernel(const float *__restrict__ X) {
#if !HAS_TC
    __shared__ __align__(16) float As[16 * 128];
    __shared__ __align__(16) float Bs[16 * 128];

    const int tid = threadIdx.x;
    const int m0 = blockIdx.x * 128;
    const int n0 = blockIdx.y * 128;
    const int tm = tid >> 4;
    const int tn = tid & 15;

    unsigned long long acc[4][8];
#pragma unroll
    for (int i = 0; i < 4; i++)
#pragma unroll
        for (int j = 0; j < 8; j++) acc[i][j] = 0ull;

    const int u0 = tid * 2;
    const int arow0 = u0 >> 2,       ac40 = u0 & 3;
    const int arow1 = (u0 + 1) >> 2, ac41 = (u0 + 1) & 3;

    const float *Xb = X + (size_t)m0 * DIMK;
    const float *Wb = scr_w + (size_t)n0 * DIMK;

    for (int kt = 0; kt < DIMK; kt += 16) {
        float4 a0 = *(const float4 *)(Xb + (size_t)arow0 * DIMK + kt + ac40 * 4);
        float4 a1 = *(const float4 *)(Xb + (size_t)arow1 * DIMK + kt + ac41 * 4);
        float4 b0 = *(const float4 *)(Wb + (size_t)arow0 * DIMK + kt + ac40 * 4);
        float4 b1 = *(const float4 *)(Wb + (size_t)arow1 * DIMK + kt + ac41 * 4);

        __syncthreads();
        {
            int k0 = ac40 * 4, k1 = ac41 * 4;
            As[(k0 + 0) * 128 + arow0] = a0.x; As[(k0 + 1) * 128 + arow0] = a0.y;
            As[(k0 + 2) * 128 + arow0] = a0.z; As[(k0 + 3) * 128 + arow0] = a0.w;
            As[(k1 + 0) * 128 + arow1] = a1.x; As[(k1 + 1) * 128 + arow1] = a1.y;
            As[(k1 + 2) * 128 + arow1] = a1.z; As[(k1 + 3) * 128 + arow1] = a1.w;
            Bs[(k0 + 0) * 128 + arow0] = b0.x; Bs[(k0 + 1) * 128 + arow0] = b0.y;
            Bs[(k0 + 2) * 128 + arow0] = b0.z; Bs[(k0 + 3) * 128 + arow0] = b0.w;
            Bs[(k1 + 0) * 128 + arow1] = b1.x; Bs[(k1 + 1) * 128 + arow1] = b1.y;
            Bs[(k1 + 2) * 128 + arow1] = b1.z; Bs[(k1 + 3) * 128 + arow1] = b1.w;
        }
        __syncthreads();

#pragma unroll
        for (int k = 0; k < 16; k++) {
            const ulonglong2 *pa = (const ulonglong2 *)&As[k * 128 + tm * 8];
            ulonglong2 av0 = pa[0];
            ulonglong2 av1 = pa[1];
            float4 bv0 = *(const float4 *)&Bs[k * 128 + tn * 8];
            float4 bv1 = *(const float4 *)&Bs[k * 128 + tn * 8 + 4];
            unsigned long long ap[4] = {av0.x, av0.y, av1.x, av1.y};
            unsigned long long bbx[8];
            bbx[0] = pack2(bv0.x, bv0.x); bbx[1] = pack2(bv0.y, bv0.y);
            bbx[2] = pack2(bv0.z, bv0.z); bbx[3] = pack2(bv0.w, bv0.w);
            bbx[4] = pack2(bv1.x, bv1.x); bbx[5] = pack2(bv1.y, bv1.y);
            bbx[6] = pack2(bv1.z, bv1.z); bbx[7] = pack2(bv1.w, bv1.w);
#pragma unroll
            for (int mp = 0; mp < 4; mp++)
#pragma unroll
                for (int n = 0; n < 8; n++)
                    ffma2(acc[mp][n], ap[mp], bbx[n]);
        }
    }

#pragma unroll
    for (int mp = 0; mp < 4; mp++) {
        float lo[8], hi[8];
#pragma unroll
        for (int n = 0; n < 8; n++) unpack2(acc[mp][n], lo[n], hi[n]);
        int mA = m0 + tm * 8 + mp * 2;
        float *outp = scr_raw + (size_t)mA * NTOT + n0 + tn * 8;
        *(float4 *)(outp)            = make_float4(lo[0], lo[1], lo[2], lo[3]);
        *(float4 *)(outp + 4)        = make_float4(lo[4], lo[5], lo[6], lo[7]);
        *(float4 *)(outp + NTOT)     = make_float4(hi[0], hi[1], hi[2], hi[3]);
        *(float4 *)(outp + NTOT + 4) = make_float4(hi[4], hi[5], hi[6], hi[7]);
    }
#endif
}

// ======================================================================
// tcgen05 GEMM (body only in arch-specific passes) — unchanged from R3
// ======================================================================
#define GK 64
#define NKC (DIMK / GK)
#define A_BYTES  (128 * 128)
#define B_BYTES  (256 * 128)
#define ST_BYTES (2 * A_BYTES + 2 * B_BYTES)          // 96 KB
#define SMEM_GEMM_TOTAL (1024 + 2 * ST_BYTES)
#define G_IDESC ((1u << 4) | (1u << 7) | (1u << 10) | ((NTOT / 8) << 17) | ((128 / 16) << 24))

extern __shared__ __align__(1024) char gsm[];

#if HAS_TC
__device__ __forceinline__ void g_load_chunk(char *stp, int m0, int kc, int tid) {
    const char *xh = (const char *)(g_xhi + (size_t)m0 * DIMK + kc * GK);
    const char *xl = (const char *)(g_xlo + (size_t)m0 * DIMK + kc * GK);
#pragma unroll
    for (int i = 0; i < 8; i++) {
        int idx = tid + i * 128;
        int row = idx >> 3, gr = idx & 7;
        uint32_t sw = SWZ(row * 128 + gr * 16);
        size_t gof = (size_t)row * (DIMK * 2) + gr * 16;
        cp_async16(stp + sw, xh + gof);
        cp_async16(stp + A_BYTES + sw, xl + gof);
    }
    const char *wh = (const char *)(g_whi + kc * GK);
    const char *wl = (const char *)(g_wlo + kc * GK);
#pragma unroll
    for (int i = 0; i < 16; i++) {
        int idx = tid + i * 128;
        int row = idx >> 3, gr = idx & 7;
        uint32_t sw = SWZ(row * 128 + gr * 16);
        size_t gof = (size_t)row * (DIMK * 2) + gr * 16;
        cp_async16(stp + 2 * A_BYTES + sw, wh + gof);
        cp_async16(stp + 2 * A_BYTES + B_BYTES + sw, wl + gof);
    }
}
#endif

__global__ __launch_bounds__(128, 1)
void mma_gemm_kernel() {
#if HAS_TC
    const int tid = threadIdx.x, wid = tid >> 5, lid = tid & 31;
    const int m0 = blockIdx.x * 128;
    uint32_t sbase = (uint32_t)__cvta_generic_to_shared(gsm);

    if (wid == 0) {
        asm volatile("tcgen05.alloc.cta_group::1.sync.aligned.shared::cta.b32 [%0], %1;"
                     :: "r"(sbase), "r"(256u) : "memory");
        asm volatile("tcgen05.relinquish_alloc_permit.cta_group::1.sync.aligned;");
    }
    if (tid == 0) { mbar_init(sbase + 16, 1); mbar_init(sbase + 24, 1); }
    __syncthreads();
    uint32_t tmem;
    asm volatile("ld.shared.b32 %0, [%1];" : "=r"(tmem) : "r"(sbase));

    g_load_chunk(gsm + 1024, m0, 0, tid);
    asm volatile("cp.async.commit_group;");
    g_load_chunk(gsm + 1024 + ST_BYTES, m0, 1, tid);
    asm volatile("cp.async.commit_group;");

    int ph0 = 0, ph1 = 0;
    for (int c = 0; c < NKC; c++) {
        int s = c & 1;
        char *stp = gsm + 1024 + s * ST_BYTES;
        uint32_t sa = sbase + 1024 + s * ST_BYTES;
        if (c < NKC - 1) asm volatile("cp.async.wait_group 1;" ::: "memory");
        else             asm volatile("cp.async.wait_group 0;" ::: "memory");
        __syncthreads();

        if (tid == 0) {
            asm volatile("fence.proxy.async.shared::cta;" ::: "memory");
            uint64_t ahi = make_desc(sa);
            uint64_t alo = make_desc(sa + A_BYTES);
            uint64_t bhi = make_desc(sa + 2 * A_BYTES);
            uint64_t blo = make_desc(sa + 2 * A_BYTES + B_BYTES);
#pragma unroll
            for (int k = 0; k < 4; k++)
                mma_f16_ss(tmem, ahi + k * 2, bhi + k * 2, G_IDESC, !(c == 0 && k == 0));
#pragma unroll
            for (int k = 0; k < 4; k++)
                mma_f16_ss(tmem, ahi + k * 2, blo + k * 2, G_IDESC, 1u);
#pragma unroll
            for (int k = 0; k < 4; k++)
                mma_f16_ss(tmem, alo + k * 2, bhi + k * 2, G_IDESC, 1u);
            asm volatile(
                "tcgen05.commit.cta_group::1.mbarrier::arrive::one.shared::cluster.b64 [%0];"
                :: "r"(sbase + 16 + s * 8) : "memory");
        }
        if (c + 2 < NKC) {
            if (s == 0) { mbar_wait(sbase + 16, ph0 & 1); ph0++; }
            else        { mbar_wait(sbase + 24, ph1 & 1); ph1++; }
            g_load_chunk(stp, m0, c + 2, tid);
            asm volatile("cp.async.commit_group;");
        }
    }
    mbar_wait(sbase + 16, ph0 & 1);
    mbar_wait(sbase + 24, ph1 & 1);
    asm volatile("tcgen05.fence::after_thread_sync;" ::: "memory");

    float *orow = scr_raw + (size_t)(m0 + wid * 32 + lid) * NTOT;
#pragma unroll 1
    for (int cb = 0; cb < 8; cb++) {
        uint32_t r[32];
        asm volatile(
            "tcgen05.ld.sync.aligned.32x32b.x32.b32 "
            "{%0, %1, %2, %3, %4, %5, %6, %7, "
            " %8, %9, %10, %11, %12, %13, %14, %15, "
            " %16, %17, %18, %19, %20, %21, %22, %23, "
            " %24, %25, %26, %27, %28, %29, %30, %31}, [%32];"
            : "=r"(r[0]), "=r"(r[1]), "=r"(r[2]), "=r"(r[3]), "=r"(r[4]), "=r"(r[5]),
              "=r"(r[6]), "=r"(r[7]), "=r"(r[8]), "=r"(r[9]), "=r"(r[10]), "=r"(r[11]),
              "=r"(r[12]), "=r"(r[13]), "=r"(r[14]), "=r"(r[15]), "=r"(r[16]), "=r"(r[17]),
              "=r"(r[18]), "=r"(r[19]), "=r"(r[20]), "=r"(r[21]), "=r"(r[22]), "=r"(r[23]),
              "=r"(r[24]), "=r"(r[25]), "=r"(r[26]), "=r"(r[27]), "=r"(r[28]), "=r"(r[29]),
              "=r"(r[30]), "=r"(r[31])
            : "r"(tmem + cb * 32));
        asm volatile("tcgen05.wait::ld.sync.aligned;" ::: "memory");
        float4 *o4 = (float4 *)(orow + cb * 32);
#pragma unroll
        for (int i = 0; i < 8; i++)
            o4[i] = make_float4(__uint_as_float(r[i * 4]), __uint_as_float(r[i * 4 + 1]),
                                __uint_as_float(r[i * 4 + 2]), __uint_as_float(r[i * 4 + 3]));
    }
    __syncthreads();
    if (wid == 0)
        asm volatile("tcgen05.dealloc.cta_group::1.sync.aligned.b32 %0, %1;"
                     :: "r"(tmem), "r"(256u));
#endif
}

// ======================================================================
// Epilogue: kn = k/(|k|+eps), g = sigmoid(beta+b)   (1 warp/row)
// ======================================================================
__global__ void epilogue_kernel(const float *__restrict__ b_beta) {
    int warp = (blockIdx.x * blockDim.x + threadIdx.x) >> 5;
    int lane = threadIdx.x & 31;
    if (warp >= MROWS) return;
    float *row = scr_raw + (size_t)warp * NTOT;
    int i0 = lane * 2;

    float2 kv = *(float2 *)(row + i0);
    float2 bt = *(float2 *)(row + 192 + i0);

    float nk = kv.x * kv.x + kv.y * kv.y;
#pragma unroll
    for (int off = 16; off; off >>= 1) nk += __shfl_xor_sync(0xffffffffu, nk, off);
    float inv = 1.0f / (sqrtf(nk) + 1e-6f);

    float gx = 1.0f / (1.0f + __expf(-(bt.x + b_beta[i0])));
    float gy = 1.0f / (1.0f + __expf(-(bt.y + b_beta[i0 + 1])));

    *(float2 *)(row + i0)       = make_float2(kv.x * inv, kv.y * inv);
    *(float2 *)(row + 192 + i0) = make_float2(gx, gy);
}

// ======================================================================
// Pair kernel: per row m, scr_pr[m] = {P1,R1,P2,R2,P3,R3,c,0}
//   P_j = kn_m . kn_{m+jB},  R_j = kn_m . q_{m+jB},  c = kn_m . q_m
// Pad rows (t >= T) are zero -> dots 0 at the boundary.
// ======================================================================
__global__ void pair_kernel() {
    int warp = (blockIdx.x * blockDim.x + threadIdx.x) >> 5;
    int lane = threadIdx.x & 31;
    if (warp >= MROWS) return;
    const float *r0 = scr_raw + (size_t)warp * NTOT;
    const float *r1 = scr_raw + (size_t)(warp + BB) * NTOT;
    const float *r2 = scr_raw + (size_t)(warp + 2 * BB) * NTOT;
    const float *r3 = scr_raw + (size_t)(warp + 3 * BB) * NTOT;
    int i0 = lane * 2;

    float2 k0 = *(const float2 *)(r0 + i0);
    float2 q0 = *(const float2 *)(r0 + 128 + i0);
    float2 k1 = *(const float2 *)(r1 + i0);
    float2 q1 = *(const float2 *)(r1 + 128 + i0);
    float2 k2 = *(const float2 *)(r2 + i0);
    float2 q2 = *(const float2 *)(r2 + 128 + i0);
    float2 k3 = *(const float2 *)(r3 + i0);
    float2 q3 = *(const float2 *)(r3 + 128 + i0);

    float c  = k0.x * q0.x + k0.y * q0.y;
    float P1 = k0.x * k1.x + k0.y * k1.y;
    float R1 = k0.x * q1.x + k0.y * q1.y;
    float P2 = k0.x * k2.x + k0.y * k2.y;
    float R2 = k0.x * q2.x + k0.y * q2.y;
    float P3 = k0.x * k3.x + k0.y * k3.y;
    float R3 = k0.x * q3.x + k0.y * q3.y;
#pragma unroll
    for (int off = 16; off; off >>= 1) {
        c  += __shfl_xor_sync(0xffffffffu, c,  off);
        P1 += __shfl_xor_sync(0xffffffffu, P1, off);
        R1 += __shfl_xor_sync(0xffffffffu, R1, off);
        P2 += __shfl_xor_sync(0xffffffffu, P2, off);
        R2 += __shfl_xor_sync(0xffffffffu, R2, off);
        P3 += __shfl_xor_sync(0xffffffffu, P3, off);
        R3 += __shfl_xor_sync(0xffffffffu, R3, off);
    }
    if (lane == 0) {
        float *pr = scr_pr + (size_t)warp * 8;
        *(float4 *)pr       = make_float4(P1, R1, P2, R2);
        *(float4 *)(pr + 4) = make_float4(P3, R3, c, 0.0f);
    }
}

// ======================================================================
// Scan with depth-4 software-pipelined lookahead.
// grid (B=16, 8 row-groups), 64 threads (8 rows x 8 lanes).
// Per step t the serial chain is only: delta_t -> FMA -> rk_{t+1}.
// ======================================================================
__device__ __forceinline__ void scan_issue(float *kn_s, float *q_s, float *v_s, float *g_s,
                                           float *pr_s, int t0, int b, int r0, int tid) {
    // kn, q: CH19 steps * 16 float4 = 304 units each
#pragma unroll
    for (int i = 0; i < 5; i++) {
        int u = tid + i * 64;
        if (u < CH19 * 16) {
            int st = u >> 4, f4 = u & 15;
            size_t m = (size_t)(t0 + st) * BB + b;
            cp_async16(kn_s + st * 64 + f4 * 4, scr_raw + m * NTOT + f4 * 4);
            cp_async16(q_s  + st * 64 + f4 * 4, scr_raw + m * NTOT + 128 + f4 * 4);
        }
    }
    {
        int st = (tid & 31) >> 1, part = tid & 1;
        size_t m = (size_t)(t0 + st) * BB + b;
        if (tid < 32) cp_async16(v_s + st * 8 + part * 4, scr_raw + m * NTOT + 64 + r0 + part * 4);
        else          cp_async16(g_s + st * 8 + part * 4, scr_raw + m * NTOT + 192 + r0 + part * 4);
    }
    if (tid < 32) {
        int st = tid >> 1, half = tid & 1;
        size_t m = (size_t)(t0 + st) * BB + b;
        cp_async16(pr_s + st * 8 + half * 4, scr_pr + m * 8 + half * 4);
    }
}

// full dot of s[8] with 8 consecutive floats at p, reduced over the 8-lane group
__device__ __forceinline__ float dot_full(const float *s, const float *p) {
    float4 a = *(const float4 *)p, b = *(const float4 *)(p + 4);
    float x = s[0] * a.x, y = s[1] * a.y;
    x = fmaf(s[2], a.z, x); y = fmaf(s[3], a.w, y);
    x = fmaf(s[4], b.x, x); y = fmaf(s[5], b.y, y);
    x = fmaf(s[6], b.z, x); y = fmaf(s[7], b.w, y);
    float r = x + y;
    r += __shfl_xor_sync(0xffffffffu, r, 1);
    r += __shfl_xor_sync(0xffffffffu, r, 2);
    r += __shfl_xor_sync(0xffffffffu, r, 4);
    return r;
}
// partial dot with only 2 reduction levels applied
__device__ __forceinline__ float dot_2lvl(const float *s, const float *p) {
    float4 a = *(const float4 *)p, b = *(const float4 *)(p + 4);
    float x = s[0] * a.x, y = s[1] * a.y;
    x = fmaf(s[2], a.z, x); y = fmaf(s[3], a.w, y);
    x = fmaf(s[4], b.x, x); y = fmaf(s[5], b.y, y);
    x = fmaf(s[6], b.z, x); y = fmaf(s[7], b.w, y);
    float r = x + y;
    r += __shfl_xor_sync(0xffffffffu, r, 1);
    r += __shfl_xor_sync(0xffffffffu, r, 2);
    return r;
}

__global__ __launch_bounds__(64) void scan_kernel(const float *__restrict__ S0,
                                                  float *__restrict__ out,
                                                  int write_sfinal) {
    __shared__ __align__(16) float sh_kn[2][CH19][64];
    __shared__ __align__(16) float sh_q [2][CH19][64];
    __shared__ __align__(16) float sh_v [2][CHUNK][8];
    __shared__ __align__(16) float sh_g [2][CHUNK][8];
    __shared__ __align__(16) float sh_pr[2][CHUNK][8];
    __shared__ float sh_out[CHUNK][8];

    const int b  = blockIdx.x;
    const int r0 = blockIdx.y * 8;
    const int tid = threadIdx.x;
    const int rl = tid >> 3;         // row-local 0..7
    const int cg = tid & 7;          // lane within row
    const int j0 = cg * 8;
    const int row = r0 + rl;
    const float mask = (cg == 0) ? 1.0f : 0.0f;

    float s[8];
    {
        const float *s0p = S0 + ((size_t)b * 64 + row) * 64 + j0;
#pragma unroll
        for (int j = 0; j < 8; j++) s[j] = s0p[j];
    }

    // ---- prologue: seed rk/rq (target 0), A (target 1, full), B (target 2, 2 lvls) ----
    float rk, rq, Ak, Aq, Bk, Bq;
    {
        const float *p0 = scr_raw + ((size_t)0 * BB + b) * NTOT;
        const float *p1 = scr_raw + ((size_t)1 * BB + b) * NTOT;
        const float *p2 = scr_raw + ((size_t)2 * BB + b) * NTOT;
        rk = dot_full(s, p0 + j0);       rq = dot_full(s, p0 + 128 + j0);
        Ak = dot_full(s, p1 + j0);       Aq = dot_full(s, p1 + 128 + j0);
        Bk = dot_2lvl(s, p2 + j0);       Bq = dot_2lvl(s, p2 + 128 + j0);
    }

    scan_issue(&sh_kn[0][0][0], &sh_q[0][0][0], &sh_v[0][0][0], &sh_g[0][0][0],
               &sh_pr[0][0][0], 0, b, r0, tid);
    asm volatile("cp.async.commit_group;");

    for (int ch = 0; ch < NCH; ch++) {
        const int pb = ch & 1;
        if (ch + 1 < NCH) {
            scan_issue(&sh_kn[pb ^ 1][0][0], &sh_q[pb ^ 1][0][0], &sh_v[pb ^ 1][0][0],
                       &sh_g[pb ^ 1][0][0], &sh_pr[pb ^ 1][0][0],
                       (ch + 1) * CHUNK, b, r0, tid);
            asm volatile("cp.async.commit_group;");
            asm volatile("cp.async.wait_group 1;");
        } else {
            asm volatile("cp.async.wait_group 0;");
        }
        __syncthreads();

#pragma unroll
        for (int st = 0; st < CHUNK; st++) {
            // B final reduction level — top of step, independent of this step's delta
            Bk += __shfl_xor_sync(0xffffffffu, Bk, 4);
            Bq += __shfl_xor_sync(0xffffffffu, Bq, 4);

            const float v = sh_v[pb][st][rl];
            const float g = sh_g[pb][st][rl];
            const float4 pr0 = *(const float4 *)&sh_pr[pb][st][0];  // P1,R1,P2,R2
            const float4 pr1 = *(const float4 *)&sh_pr[pb][st][4];  // P3,R3,c,0

            // ---- serial fast path ----
            const float delta = v - rk;
            const float Sq = fmaf(g, rq, delta * pr1.z);
            if (cg == 0) {
                float sg = 1.0f / (1.0f + __expf(-Sq));
                sh_out[st][rl] = Sq * Sq * sg;       // Sq * silu(Sq)
            }

            // A -> rk for next step (2 FMAs after delta: the whole serial chain)
            const float rk_n = fmaf(g, Ak, delta * pr0.x);
            const float rq_n = fmaf(g, Aq, delta * pr0.y);

            // B uniform correction (after its final level above)
            const float Bk_n = fmaf(g, Bk, delta * pr0.z);
            const float Bq_n = fmaf(g, Bq, delta * pr0.w);

            // ---- create C: dot of OLD state with kn_{t+3}, q_{t+3} ----
            const float4 k3a = *(const float4 *)&sh_kn[pb][st + 3][j0];
            const float4 k3b = *(const float4 *)&sh_kn[pb][st + 3][j0 + 4];
            const float4 q3a = *(const float4 *)&sh_q[pb][st + 3][j0];
            const float4 q3b = *(const float4 *)&sh_q[pb][st + 3][j0 + 4];
            float cx = s[0] * k3a.x, cy = s[1] * k3a.y;
            float dx = s[0] * q3a.x, dy = s[1] * q3a.y;
            cx = fmaf(s[2], k3a.z, cx); cy = fmaf(s[3], k3a.w, cy);
            dx = fmaf(s[2], q3a.z, dx); dy = fmaf(s[3], q3a.w, dy);
            cx = fmaf(s[4], k3b.x, cx); cy = fmaf(s[5], k3b.y, cy);
            dx = fmaf(s[4], q3b.x, dx); dy = fmaf(s[5], q3b.y, dy);
            cx = fmaf(s[6], k3b.z, cx); cy = fmaf(s[7], k3b.w, cy);
            dx = fmaf(s[6], q3b.z, dx); dy = fmaf(s[7], q3b.w, dy);
            float Ck = cx + cy;
            float Cq = dx + dy;

            // masked single-lane correction on the per-lane partials (pre-reduction)
            const float md = mask * delta;
            Ck = fmaf(g, Ck, md * pr1.x);
            Cq = fmaf(g, Cq, md * pr1.y);
            // C reduction levels 1,2
            Ck += __shfl_xor_sync(0xffffffffu, Ck, 1);
            Cq += __shfl_xor_sync(0xffffffffu, Cq, 1);
            Ck += __shfl_xor_sync(0xffffffffu, Ck, 2);
            Cq += __shfl_xor_sync(0xffffffffu, Cq, 2);

            // ---- state update with kn_t ----
            const float4 k0a = *(const float4 *)&sh_kn[pb][st][j0];
            const float4 k0b = *(const float4 *)&sh_kn[pb][st][j0 + 4];
            s[0] = fmaf(g, s[0], delta * k0a.x);
            s[1] = fmaf(g, s[1], delta * k0a.y);
            s[2] = fmaf(g, s[2], delta * k0a.z);
            s[3] = fmaf(g, s[3], delta * k0a.w);
            s[4] = fmaf(g, s[4], delta * k0b.x);
            s[5] = fmaf(g, s[5], delta * k0b.y);
            s[6] = fmaf(g, s[6], delta * k0b.z);
            s[7] = fmaf(g, s[7], delta * k0b.w);

            // rotate pipeline
            rk = rk_n; rq = rq_n;
            Ak = Bk_n; Aq = Bq_n;
            Bk = Ck;   Bq = Cq;
        }
        __syncthreads();

        const int t0 = ch * CHUNK;
#pragma unroll
        for (int uq = 0; uq < 2; uq++) {
            int idx = tid + uq * 64;
            int st2 = idx >> 3, r = idx & 7;
            out[(size_t)(t0 + st2) * (BB * NN) + b * NN + r0 + r] = sh_out[st2][r];
        }
    }

    if (write_sfinal) {
        float *sf = out + (size_t)TT * BB * NN + ((size_t)b * 64 + row) * 64 + j0;
        *(float4 *)sf       = make_float4(s[0], s[1], s[2], s[3]);
        *(float4 *)(sf + 4) = make_float4(s[4], s[5], s[6], s[7]);
    }
}

// ======================================================================
extern "C" void kernel_launch(void *const *d_in, const int *in_sizes, int n_in,
                              void *d_out, int out_size) {
    const float *x  = (const float *)d_in[0];
    const float *S0 = (const float *)d_in[1];
    const float *Wk = (const float *)d_in[2];
    const float *Wv = (const float *)d_in[3];
    const float *Wq = (const float *)d_in[4];
    const float *Wb = (const float *)d_in[5];
    const float *bb = (const float *)d_in[6];
    float *out = (float *)d_out;

    cudaFuncSetAttribute(mma_gemm_kernel, cudaFuncAttributeMaxDynamicSharedMemorySize,
                         SMEM_GEMM_TOTAL);

    copyw_kernel<<<1024, 256>>>(Wk, Wv, Wq, Wb);
    convw_kernel<<<256, 256>>>(Wk, Wv, Wq, Wb);
    convx_kernel<<<32768, 256>>>(x);

    mma_gemm_kernel<<<MROWS / 128, 128, SMEM_GEMM_TOTAL>>>();
    fb_gemm_kernel<<<dim3(MROWS / 128, 2), 256>>>(x);

    epilogue_kernel<<<4096, 256>>>(bb);
    pair_kernel<<<4096, 256>>>();

    int ws = (out_size >= TT * BB * NN + BB * NN * NN) ? 1 : 0;
    scan_kernel<<<dim3(BB, 8), 64>>>(S0, out, ws);
}

// round 11
// speedup vs baseline: 1.1307x; 1.1307x over previous
#include <cuda_runtime.h>
#include <cuda_bf16.h>
#include <cstdint>
#include <cstddef>

#define TT 2048
#define BB 16
#define DIMK 1024
#define NN 64
#define NTOT 256
#define MROWS (TT*BB)
#define LC 16
#define NCH (TT/LC)

#if defined(__CUDA_ARCH__) && (__CUDA_ARCH__ >= 1000) && \
    (defined(__CUDA_ARCH_FEAT_SM103_ALL) || defined(__CUDA_ARCH_FEAT_SM100_ALL))
#define HAS_TC 1
#else
#define HAS_TC 0
#endif

__device__ __align__(128) __nv_bfloat16 g_xhi[(size_t)MROWS * DIMK];
__device__ __align__(128) __nv_bfloat16 g_xlo[(size_t)MROWS * DIMK];
__device__ __align__(128) __nv_bfloat16 g_whi[NTOT * DIMK];
__device__ __align__(128) __nv_bfloat16 g_wlo[NTOT * DIMK];
__device__ __align__(128) float scr_w[NTOT * DIMK];
__device__ __align__(128) float scr_raw[(size_t)MROWS * NTOT];
__device__ __align__(128) float scr_kk[(size_t)BB * NCH * 256];
__device__ __align__(128) float scr_kq[(size_t)BB * NCH * 256];

#define SWZ(off) ((off) ^ (((off) >> 3) & 0x70))

__device__ __forceinline__ void cp_async16(void *smem_dst, const void *gsrc) {
    unsigned sa = (unsigned)__cvta_generic_to_shared(smem_dst);
    asm volatile("cp.async.ca.shared.global [%0], [%1], 16;" :: "r"(sa), "l"(gsrc));
}
__device__ __forceinline__ unsigned long long pack2(float x, float y) {
    unsigned long long r; asm("mov.b64 %0, {%1, %2};" : "=l"(r) : "f"(x), "f"(y)); return r;
}
__device__ __forceinline__ void unpack2(unsigned long long v, float &x, float &y) {
    asm("mov.b64 {%0, %1}, %2;" : "=f"(x), "=f"(y) : "l"(v));
}
__device__ __forceinline__ void ffma2(unsigned long long &c, unsigned long long a, unsigned long long b) {
    asm("fma.rn.f32x2 %0, %1, %2, %0;" : "+l"(c) : "l"(a), "l"(b));
}
__device__ __forceinline__ void split4(float4 v, uint2 &uh, uint2 &ul) {
    __nv_bfloat16 h0 = __float2bfloat16(v.x), h1 = __float2bfloat16(v.y);
    __nv_bfloat16 h2 = __float2bfloat16(v.z), h3 = __float2bfloat16(v.w);
    __nv_bfloat16 l0 = __float2bfloat16(v.x - __bfloat162float(h0));
    __nv_bfloat16 l1 = __float2bfloat16(v.y - __bfloat162float(h1));
    __nv_bfloat16 l2 = __float2bfloat16(v.z - __bfloat162float(h2));
    __nv_bfloat16 l3 = __float2bfloat16(v.w - __bfloat162float(h3));
    uh.x = ((uint32_t)__bfloat16_as_ushort(h1) << 16) | __bfloat16_as_ushort(h0);
    uh.y = ((uint32_t)__bfloat16_as_ushort(h3) << 16) | __bfloat16_as_ushort(h2);
    ul.x = ((uint32_t)__bfloat16_as_ushort(l1) << 16) | __bfloat16_as_ushort(l0);
    ul.y = ((uint32_t)__bfloat16_as_ushort(l3) << 16) | __bfloat16_as_ushort(l2);
}

#if HAS_TC
__device__ __forceinline__ uint64_t make_desc(uint32_t a) {
    return ((uint64_t)2 << 61) | ((uint64_t)1 << 46) | ((uint64_t)64 << 32) |
           ((uint64_t)1 << 16) | ((a >> 4) & 0x3FFF);
}
__device__ __forceinline__ void mbar_init(uint32_t addr, uint32_t cnt) {
    asm volatile("mbarrier.init.shared.b64 [%0], %1;" :: "r"(addr), "r"(cnt) : "memory");
}
__device__ __forceinline__ void mbar_wait(uint32_t addr, uint32_t parity) {
    uint32_t done;
    asm volatile("{\n\t.reg .pred p;\n\t"
        "mbarrier.try_wait.parity.acquire.cta.shared::cta.b64 p, [%1], %2;\n\t"
        "selp.b32 %0, 1, 0, p;\n\t}" : "=r"(done) : "r"(addr), "r"(parity) : "memory");
    if (!done) {
        asm volatile("{\n\t.reg .pred P1;\n\t"
            "WL_%=:\n\t"
            "mbarrier.try_wait.parity.acquire.cta.shared::cta.b64 P1, [%0], %1, 0x989680;\n\t"
            "@P1 bra.uni WD_%=;\n\tbra.uni WL_%=;\n\tWD_%=:\n\t}"
            :: "r"(addr), "r"(parity) : "memory");
    }
}
__device__ __forceinline__ void mma_f16_ss(uint32_t d, uint64_t a, uint64_t b,
                                           uint32_t idesc, uint32_t en) {
    asm volatile("{\n\t.reg .pred p;\n\t"
        "setp.ne.u32 p, %5, 0;\n\t"
        "tcgen05.mma.cta_group::1.kind::f16 [%0], %1, %2, %3, {%4, %4, %4, %4}, p;\n\t}"
        :: "r"(d), "l"(a), "l"(b), "r"(idesc), "r"(0u), "r"(en) : "memory");
}
#endif

__global__ void copyw_kernel(const float *__restrict__ wk, const float *__restrict__ wv,
                             const float *__restrict__ wq, const float *__restrict__ wb) {
#if !HAS_TC
    int i = blockIdx.x * 256 + threadIdx.x;
    int sel = i >> 16, off = i & 65535;
    const float *src = (sel == 0) ? wk : (sel == 1) ? wv : (sel == 2) ? wq : wb;
    scr_w[i] = src[off];
#endif
}

__global__ void convw_kernel(const float *__restrict__ wk, const float *__restrict__ wv,
                             const float *__restrict__ wq, const float *__restrict__ wb) {
#if HAS_TC
    int g = blockIdx.x * 256 + threadIdx.x;
    int i4 = g * 4;
    int n = i4 >> 10, k = i4 & 1023;
    int sel = n >> 6, r = n & 63;
    const float *src = (sel == 0) ? wk : (sel == 1) ? wv : (sel == 2) ? wq : wb;
    float4 v = *(const float4 *)(src + (size_t)r * DIMK + k);
    uint2 uh, ul; split4(v, uh, ul);
    *(uint2 *)(g_whi + i4) = uh; *(uint2 *)(g_wlo + i4) = ul;
#endif
}

__global__ void convx_kernel(const float *__restrict__ x) {
#if HAS_TC
    size_t i4 = ((size_t)blockIdx.x * 256 + threadIdx.x) * 4;
    float4 v = *(const float4 *)(x + i4);
    uint2 uh, ul; split4(v, uh, ul);
    *(uint2 *)(g_xhi + i4) = uh; *(uint2 *)(g_xlo + i4) = ul;
#endif
}

__global__ __launch_bounds__(256, 2) void fb_gemm_kernel(const float *__restrict__ X) {
#if !HAS_TC
    __shared__ __align__(16) float As[16 * 128];
    __shared__ __align__(16) float Bs[16 * 128];
    const int tid = threadIdx.x;
    const int m0 = blockIdx.x * 128, n0 = blockIdx.y * 128;
    const int tm = tid >> 4, tn = tid & 15;
    unsigned long long acc[4][8];
#pragma unroll
    for (int i = 0; i < 4; i++)
#pragma unroll
        for (int j = 0; j < 8; j++) acc[i][j] = 0ull;
    const int u0 = tid * 2;
    const int arow0 = u0 >> 2, ac40 = u0 & 3;
    const int arow1 = (u0 + 1) >> 2, ac41 = (u0 + 1) & 3;
    const float *Xb = X + (size_t)m0 * DIMK;
    const float *Wb = scr_w + (size_t)n0 * DIMK;
    for (int kt = 0; kt < DIMK; kt += 16) {
        float4 a0 = *(const float4 *)(Xb + (size_t)arow0 * DIMK + kt + ac40 * 4);
        float4 a1 = *(const float4 *)(Xb + (size_t)arow1 * DIMK + kt + ac41 * 4);
        float4 b0 = *(const float4 *)(Wb + (size_t)arow0 * DIMK + kt + ac40 * 4);
        float4 b1 = *(const float4 *)(Wb + (size_t)arow1 * DIMK + kt + ac41 * 4);
        __syncthreads();
        {
            int k0 = ac40 * 4, k1 = ac41 * 4;
            As[(k0+0)*128+arow0]=a0.x; As[(k0+1)*128+arow0]=a0.y;
            As[(k0+2)*128+arow0]=a0.z; As[(k0+3)*128+arow0]=a0.w;
            As[(k1+0)*128+arow1]=a1.x; As[(k1+1)*128+arow1]=a1.y;
            As[(k1+2)*128+arow1]=a1.z; As[(k1+3)*128+arow1]=a1.w;
            Bs[(k0+0)*128+arow0]=b0.x; Bs[(k0+1)*128+arow0]=b0.y;
            Bs[(k0+2)*128+arow0]=b0.z; Bs[(k0+3)*128+arow0]=b0.w;
            Bs[(k1+0)*128+arow1]=b1.x; Bs[(k1+1)*128+arow1]=b1.y;
            Bs[(k1+2)*128+arow1]=b1.z; Bs[(k1+3)*128+arow1]=b1.w;
        }
        __syncthreads();
#pragma unroll
        for (int k = 0; k < 16; k++) {
            const ulonglong2 *pa = (const ulonglong2 *)&As[k * 128 + tm * 8];
            ulonglong2 av0 = pa[0], av1 = pa[1];
            float4 bv0 = *(const float4 *)&Bs[k * 128 + tn * 8];
            float4 bv1 = *(const float4 *)&Bs[k * 128 + tn * 8 + 4];
            unsigned long long ap[4] = {av0.x, av0.y, av1.x, av1.y};
            unsigned long long bbx[8];
            bbx[0]=pack2(bv0.x,bv0.x); bbx[1]=pack2(bv0.y,bv0.y);
            bbx[2]=pack2(bv0.z,bv0.z); bbx[3]=pack2(bv0.w,bv0.w);
            bbx[4]=pack2(bv1.x,bv1.x); bbx[5]=pack2(bv1.y,bv1.y);
            bbx[6]=pack2(bv1.z,bv1.z); bbx[7]=pack2(bv1.w,bv1.w);
#pragma unroll
            for (int mp = 0; mp < 4; mp++)
#pragma unroll
                for (int n = 0; n < 8; n++) ffma2(acc[mp][n], ap[mp], bbx[n]);
        }
    }
#pragma unroll
    for (int mp = 0; mp < 4; mp++) {
        float lo[8], hi[8];
#pragma unroll
        for (int n = 0; n < 8; n++) unpack2(acc[mp][n], lo[n], hi[n]);
        int mA = m0 + tm * 8 + mp * 2;
        float *outp = scr_raw + (size_t)mA * NTOT + n0 + tn * 8;
        *(float4 *)(outp)            = make_float4(lo[0], lo[1], lo[2], lo[3]);
        *(float4 *)(outp + 4)        = make_float4(lo[4], lo[5], lo[6], lo[7]);
        *(float4 *)(outp + NTOT)     = make_float4(hi[0], hi[1], hi[2], hi[3]);
        *(float4 *)(outp + NTOT + 4) = make_float4(hi[4], hi[5], hi[6], hi[7]);
    }
#endif
}

#define GK 64
#define NKC (DIMK / GK)
#define A_BYTES (128 * 128)
#define B_BYTES (256 * 128)
#define ST_BYTES (2 * A_BYTES + 2 * B_BYTES)
#define SMEM_GEMM_TOTAL (1024 + 2 * ST_BYTES)
#define G_IDESC ((1u << 4) | (1u << 7) | (1u << 10) | ((NTOT / 8) << 17) | ((128 / 16) << 24))

extern __shared__ __align__(1024) char gsm[];

#if HAS_TC
__device__ __forceinline__ void g_load_chunk(char *stp, int m0, int kc, int tid) {
    const char *xh = (const char *)(g_xhi + (size_t)m0 * DIMK + kc * GK);
    const char *xl = (const char *)(g_xlo + (size_t)m0 * DIMK + kc * GK);
#pragma unroll
    for (int i = 0; i < 8; i++) {
        int idx = tid + i * 128;
        int row = idx >> 3, gr = idx & 7;
        uint32_t sw = SWZ(row * 128 + gr * 16);
        size_t gof = (size_t)row * (DIMK * 2) + gr * 16;
        cp_async16(stp + sw, xh + gof);
        cp_async16(stp + A_BYTES + sw, xl + gof);
    }
    const char *wh = (const char *)(g_whi + kc * GK);
    const char *wl = (const char *)(g_wlo + kc * GK);
#pragma unroll
    for (int i = 0; i < 16; i++) {
        int idx = tid + i * 128;
        int row = idx >> 3, gr = idx & 7;
        uint32_t sw = SWZ(row * 128 + gr * 16);
        size_t gof = (size_t)row * (DIMK * 2) + gr * 16;
        cp_async16(stp + 2 * A_BYTES + sw, wh + gof);
        cp_async16(stp + 2 * A_BYTES + B_BYTES + sw, wl + gof);
    }
}
#endif

__global__ __launch_bounds__(128, 1)
void mma_gemm_kernel() {
#if HAS_TC
    const int tid = threadIdx.x, wid = tid >> 5, lid = tid & 31;
    const int m0 = blockIdx.x * 128;
    uint32_t sbase = (uint32_t)__cvta_generic_to_shared(gsm);
    if (wid == 0) {
        asm volatile("tcgen05.alloc.cta_group::1.sync.aligned.shared::cta.b32 [%0], %1;"
                     :: "r"(sbase), "r"(256u) : "memory");
        asm volatile("tcgen05.relinquish_alloc_permit.cta_group::1.sync.aligned;");
    }
    if (tid == 0) { mbar_init(sbase + 16, 1); mbar_init(sbase + 24, 1); }
    __syncthreads();
    uint32_t tmem;
    asm volatile("ld.shared.b32 %0, [%1];" : "=r"(tmem) : "r"(sbase));
    g_load_chunk(gsm + 1024, m0, 0, tid);
    asm volatile("cp.async.commit_group;");
    g_load_chunk(gsm + 1024 + ST_BYTES, m0, 1, tid);
    asm volatile("cp.async.commit_group;");
    int ph0 = 0, ph1 = 0;
    for (int c = 0; c < NKC; c++) {
        int s = c & 1;
        char *stp = gsm + 1024 + s * ST_BYTES;
        uint32_t sa = sbase + 1024 + s * ST_BYTES;
        if (c < NKC - 1) asm volatile("cp.async.wait_group 1;" ::: "memory");
        else             asm volatile("cp.async.wait_group 0;" ::: "memory");
        __syncthreads();
        if (tid == 0) {
            asm volatile("fence.proxy.async.shared::cta;" ::: "memory");
            uint64_t ahi = make_desc(sa), alo = make_desc(sa + A_BYTES);
            uint64_t bhi = make_desc(sa + 2 * A_BYTES), blo = make_desc(sa + 2 * A_BYTES + B_BYTES);
#pragma unroll
            for (int k = 0; k < 4; k++)
                mma_f16_ss(tmem, ahi + k * 2, bhi + k * 2, G_IDESC, !(c == 0 && k == 0));
#pragma unroll
            for (int k = 0; k < 4; k++)
                mma_f16_ss(tmem, ahi + k * 2, blo + k * 2, G_IDESC, 1u);
#pragma unroll
            for (int k = 0; k < 4; k++)
                mma_f16_ss(tmem, alo + k * 2, bhi + k * 2, G_IDESC, 1u);
            asm volatile(
                "tcgen05.commit.cta_group::1.mbarrier::arrive::one.shared::cluster.b64 [%0];"
                :: "r"(sbase + 16 + s * 8) : "memory");
        }
        if (c + 2 < NKC) {
            if (s == 0) { mbar_wait(sbase + 16, ph0 & 1); ph0++; }
            else        { mbar_wait(sbase + 24, ph1 & 1); ph1++; }
            g_load_chunk(stp, m0, c + 2, tid);
            asm volatile("cp.async.commit_group;");
        }
    }
    mbar_wait(sbase + 16, ph0 & 1);
    mbar_wait(sbase + 24, ph1 & 1);
    asm volatile("tcgen05.fence::after_thread_sync;" ::: "memory");
    float *orow = scr_raw + (size_t)(m0 + wid * 32 + lid) * NTOT;
#pragma unroll 1
    for (int cb = 0; cb < 8; cb++) {
        uint32_t r[32];
        asm volatile(
            "tcgen05.ld.sync.aligned.32x32b.x32.b32 "
            "{%0, %1, %2, %3, %4, %5, %6, %7, %8, %9, %10, %11, %12, %13, %14, %15, "
            " %16, %17, %18, %19, %20, %21, %22, %23, %24, %25, %26, %27, %28, %29, %30, %31}, [%32];"
            : "=r"(r[0]),"=r"(r[1]),"=r"(r[2]),"=r"(r[3]),"=r"(r[4]),"=r"(r[5]),
              "=r"(r[6]),"=r"(r[7]),"=r"(r[8]),"=r"(r[9]),"=r"(r[10]),"=r"(r[11]),
              "=r"(r[12]),"=r"(r[13]),"=r"(r[14]),"=r"(r[15]),"=r"(r[16]),"=r"(r[17]),
              "=r"(r[18]),"=r"(r[19]),"=r"(r[20]),"=r"(r[21]),"=r"(r[22]),"=r"(r[23]),
              "=r"(r[24]),"=r"(r[25]),"=r"(r[26]),"=r"(r[27]),"=r"(r[28]),"=r"(r[29]),
              "=r"(r[30]),"=r"(r[31])
            : "r"(tmem + cb * 32));
        asm volatile("tcgen05.wait::ld.sync.aligned;" ::: "memory");
        float4 *o4 = (float4 *)(orow + cb * 32);
#pragma unroll
        for (int i = 0; i < 8; i++)
            o4[i] = make_float4(__uint_as_float(r[i*4]), __uint_as_float(r[i*4+1]),
                                __uint_as_float(r[i*4+2]), __uint_as_float(r[i*4+3]));
    }
    __syncthreads();
    if (wid == 0)
        asm volatile("tcgen05.dealloc.cta_group::1.sync.aligned.b32 %0, %1;"
                     :: "r"(tmem), "r"(256u));
#endif
}

// ===== epilogue: kn normalize + gate =====
__global__ void epilogue_kernel(const float *__restrict__ b_beta) {
    int warp = (blockIdx.x * blockDim.x + threadIdx.x) >> 5;
    int lane = threadIdx.x & 31;
    if (warp >= MROWS) return;
    float *row = scr_raw + (size_t)warp * NTOT;
    int i0 = lane * 2;
    float2 kv = *(float2 *)(row + i0);
    float2 bt = *(float2 *)(row + 192 + i0);
    float nk = kv.x * kv.x + kv.y * kv.y;
#pragma unroll
    for (int off = 16; off; off >>= 1) nk += __shfl_xor_sync(0xffffffffu, nk, off);
    float inv = 1.0f / (sqrtf(nk) + 1e-6f);
    float gx = 1.0f / (1.0f + __expf(-(bt.x + b_beta[i0])));
    float gy = 1.0f / (1.0f + __expf(-(bt.y + b_beta[i0 + 1])));
    *(float2 *)(row + i0)       = make_float2(kv.x * inv, kv.y * inv);
    *(float2 *)(row + 192 + i0) = make_float2(gx, gy);
}

// ===== gram: per (b,chunk) KK[j][t]=kn_j.kn_t, KQ[j][t]=kn_j.q_t =====
// FIXED: exactly 256 float4 loads per array (t = tid>>4 in 0..15)
__global__ __launch_bounds__(256) void gram_kernel() {
    __shared__ __align__(16) float kn_s[16 * 68], q_s[16 * 68];
    const int gb = blockIdx.x;            // 0..2047
    const int ch = gb >> 4, b = gb & 15;
    const int tid = threadIdx.x;
    {
        int t = tid >> 4, c4 = tid & 15;  // t in 0..15, c4 in 0..15
        size_t m = (size_t)(ch * 16 + t) * BB + b;
        float4 a = *(const float4 *)(scr_raw + m * NTOT + c4 * 4);
        float4 c = *(const float4 *)(scr_raw + m * NTOT + 128 + c4 * 4);
        *(float4 *)(kn_s + t * 68 + c4 * 4) = a;
        *(float4 *)(q_s  + t * 68 + c4 * 4) = c;
    }
    __syncthreads();
    const int j = tid >> 4, t = tid & 15;
    float ak = 0.f, aq = 0.f;
#pragma unroll
    for (int c4 = 0; c4 < 16; c4++) {
        float4 a  = *(const float4 *)(kn_s + j * 68 + c4 * 4);
        float4 bk = *(const float4 *)(kn_s + t * 68 + c4 * 4);
        float4 bq = *(const float4 *)(q_s  + t * 68 + c4 * 4);
        ak = fmaf(a.x,bk.x,fmaf(a.y,bk.y,fmaf(a.z,bk.z,fmaf(a.w,bk.w,ak))));
        aq = fmaf(a.x,bq.x,fmaf(a.y,bq.y,fmaf(a.z,bq.z,fmaf(a.w,bq.w,aq))));
    }
    scr_kk[(size_t)gb * 256 + j * 16 + t] = ak;
    scr_kq[(size_t)gb * 256 + j * 16 + t] = aq;
}

// ===== WY chunked scan: grid (16 b, 8 rowgroups), 64 threads =====
struct __align__(16) ScanBuf {
    float kn[16 * 68], q[16 * 68];
    float v[16 * 8], g[16 * 8];
    float kk[256], kq[256];
};

__device__ __forceinline__ void wy_issue(ScanBuf *sb, int ch, int b, int r0, int tid) {
#pragma unroll
    for (int i = 0; i < 11; i++) {
        int u = tid + i * 64;
        if (u < 512) {
            int t = (u & 255) >> 4, f4 = u & 15;
            size_t m = (size_t)(ch * 16 + t) * BB + b;
            if (u < 256) cp_async16(sb->kn + t * 68 + f4 * 4, scr_raw + m * NTOT + f4 * 4);
            else         cp_async16(sb->q  + t * 68 + f4 * 4, scr_raw + m * NTOT + 128 + f4 * 4);
        } else if (u < 576) {
            int w = u - 512;
            int t = (w & 31) >> 1, part = w & 1;
            size_t m = (size_t)(ch * 16 + t) * BB + b;
            if (w < 32) cp_async16(sb->v + t * 8 + part * 4, scr_raw + m * NTOT + 64 + r0 + part * 4);
            else        cp_async16(sb->g + t * 8 + part * 4, scr_raw + m * NTOT + 192 + r0 + part * 4);
        } else {
            int w = u - 576;
            size_t base = (size_t)(ch * 16 + b) * 256 + (w & 63) * 4;
            if (w < 64) cp_async16(sb->kk + (w & 63) * 4, scr_kk + base);
            else        cp_async16(sb->kq + (w & 63) * 4, scr_kq + base);
        }
    }
}

__global__ __launch_bounds__(64) void wy_scan_kernel(const float *__restrict__ S0,
                                                     float *__restrict__ out,
                                                     int write_sfinal) {
    __shared__ ScanBuf sb[2];
    __shared__ __align__(16) float S_s[8 * 68];
    __shared__ __align__(16) float A_s[16 * 8], Aq_s[16 * 8];
    __shared__ float carr[8 * 17];
    __shared__ float sh_out[16 * 8];

    const int b = blockIdx.x, r0 = blockIdx.y * 8;
    const int tid = threadIdx.x;
    const int rl = tid >> 3, cg = tid & 7;

    {
        const float *sp = S0 + ((size_t)b * 64 + r0 + rl) * 64 + cg * 8;
        float4 a = *(const float4 *)sp, c = *(const float4 *)(sp + 4);
        *(float4 *)(S_s + rl * 68 + cg * 8)     = a;
        *(float4 *)(S_s + rl * 68 + cg * 8 + 4) = c;
    }

    wy_issue(&sb[0], 0, b, r0, tid);
    asm volatile("cp.async.commit_group;");

    for (int ch = 0; ch < NCH; ch++) {
        const int pb = ch & 1;
        ScanBuf *B = &sb[pb];
        if (ch + 1 < NCH) {
            wy_issue(&sb[pb ^ 1], ch + 1, b, r0, tid);
            asm volatile("cp.async.commit_group;");
            asm volatile("cp.async.wait_group 1;");
        } else {
            asm volatile("cp.async.wait_group 0;");
        }
        __syncthreads();

        // ph1: A[t][rl] = S_row . kn_t, Aq = S_row . q_t ; thread does t=cg, cg+8
        {
            const int t0 = cg, t1 = cg + 8;
            float a0=0.f,a1=0.f,b0=0.f,b1=0.f;
#pragma unroll
            for (int s4 = 0; s4 < 16; s4++) {
                float4 sv = *(const float4 *)(S_s + rl * 68 + s4 * 4);
                float4 k0 = *(const float4 *)(B->kn + t0 * 68 + s4 * 4);
                float4 k1 = *(const float4 *)(B->kn + t1 * 68 + s4 * 4);
                float4 q0 = *(const float4 *)(B->q  + t0 * 68 + s4 * 4);
                float4 q1 = *(const float4 *)(B->q  + t1 * 68 + s4 * 4);
                a0 = fmaf(sv.x,k0.x,fmaf(sv.y,k0.y,fmaf(sv.z,k0.z,fmaf(sv.w,k0.w,a0))));
                a1 = fmaf(sv.x,k1.x,fmaf(sv.y,k1.y,fmaf(sv.z,k1.z,fmaf(sv.w,k1.w,a1))));
                b0 = fmaf(sv.x,q0.x,fmaf(sv.y,q0.y,fmaf(sv.z,q0.z,fmaf(sv.w,q0.w,b0))));
                b1 = fmaf(sv.x,q1.x,fmaf(sv.y,q1.y,fmaf(sv.z,q1.z,fmaf(sv.w,q1.w,b1))));
            }
            A_s [t0 * 8 + rl] = a0;  A_s [t1 * 8 + rl] = a1;
            Aq_s[t0 * 8 + rl] = b0;  Aq_s[t1 * 8 + rl] = b1;
        }
        __syncthreads();

        // ph2: forward substitution, threads 0..7 = rows
        if (tid < 8) {
            const int row = tid;
            float c[16];
            float G = 1.0f;
#pragma unroll
            for (int t = 0; t < 16; t++) {
                float a  = A_s [t * 8 + row];
                float aq = Aq_s[t * 8 + row];
                float vt = B->v[t * 8 + row];
                float gt = B->g[t * 8 + row];
                float d1a = 0.f, d1b = 0.f;
#pragma unroll
                for (int j = 0; j < 16; j++) {
                    if (j < t) {
                        float p = c[j] * B->kk[j * 16 + t];
                        if (j & 1) d1b += p; else d1a += p;
                    }
                }
                float delta = vt - fmaf(G, a, d1a + d1b);
                G *= gt;
#pragma unroll
                for (int j = 0; j < 16; j++) if (j < t) c[j] *= gt;
                c[t] = delta;
                float d2a = 0.f, d2b = 0.f;
#pragma unroll
                for (int j = 0; j < 16; j++) {
                    if (j <= t) {
                        float p = c[j] * B->kq[j * 16 + t];
                        if (j & 1) d2b += p; else d2a += p;
                    }
                }
                float Sq = fmaf(G, aq, d2a + d2b);
                float sg = 1.0f / (1.0f + __expf(-Sq));
                sh_out[t * 8 + row] = Sq * Sq * sg;
            }
#pragma unroll
            for (int j = 0; j < 16; j++) carr[row * 17 + j] = c[j];
            carr[row * 17 + 16] = G;
        }
        __syncthreads();

        // ph3: S = G_L * S + sum_j c_j * kn_j
        {
            float gl = carr[rl * 17 + 16];
            float4 s0 = *(const float4 *)(S_s + rl * 68 + cg * 8);
            float4 s1 = *(const float4 *)(S_s + rl * 68 + cg * 8 + 4);
            s0.x *= gl; s0.y *= gl; s0.z *= gl; s0.w *= gl;
            s1.x *= gl; s1.y *= gl; s1.z *= gl; s1.w *= gl;
#pragma unroll
            for (int j = 0; j < 16; j++) {
                float cj = carr[rl * 17 + j];
                float4 k0 = *(const float4 *)(B->kn + j * 68 + cg * 8);
                float4 k1 = *(const float4 *)(B->kn + j * 68 + cg * 8 + 4);
                s0.x = fmaf(cj, k0.x, s0.x); s0.y = fmaf(cj, k0.y, s0.y);
                s0.z = fmaf(cj, k0.z, s0.z); s0.w = fmaf(cj, k0.w, s0.w);
                s1.x = fmaf(cj, k1.x, s1.x); s1.y = fmaf(cj, k1.y, s1.y);
                s1.z = fmaf(cj, k1.z, s1.z); s1.w = fmaf(cj, k1.w, s1.w);
            }
            *(float4 *)(S_s + rl * 68 + cg * 8)     = s0;
            *(float4 *)(S_s + rl * 68 + cg * 8 + 4) = s1;
        }
        __syncthreads();

        // ph4: flush outputs
        const int t0c = ch * 16;
#pragma unroll
        for (int u = 0; u < 2; u++) {
            int idx = tid + u * 64;
            int t = idx >> 3, r = idx & 7;
            out[(size_t)(t0c + t) * (BB * NN) + b * NN + r0 + r] = sh_out[t * 8 + r];
        }
    }

    if (write_sfinal) {
        float *sf = out + (size_t)TT * BB * NN + ((size_t)b * 64 + r0 + rl) * 64 + cg * 8;
        *(float4 *)sf       = *(const float4 *)(S_s + rl * 68 + cg * 8);
        *(float4 *)(sf + 4) = *(const float4 *)(S_s + rl * 68 + cg * 8 + 4);
    }
}

// ======================================================================
extern "C" void kernel_launch(void *const *d_in, const int *in_sizes, int n_in,
                              void *d_out, int out_size) {
    const float *x  = (const float *)d_in[0];
    const float *S0 = (const float *)d_in[1];
    const float *Wk = (const float *)d_in[2];
    const float *Wv = (const float *)d_in[3];
    const float *Wq = (const float *)d_in[4];
    const float *Wb = (const float *)d_in[5];
    const float *bb = (const float *)d_in[6];
    float *out = (float *)d_out;

    cudaFuncSetAttribute(mma_gemm_kernel, cudaFuncAttributeMaxDynamicSharedMemorySize,
                         SMEM_GEMM_TOTAL);

    copyw_kernel<<<1024, 256>>>(Wk, Wv, Wq, Wb);
    convw_kernel<<<256, 256>>>(Wk, Wv, Wq, Wb);
    convx_kernel<<<32768, 256>>>(x);

    mma_gemm_kernel<<<MROWS / 128, 128, SMEM_GEMM_TOTAL>>>();
    fb_gemm_kernel<<<dim3(MROWS / 128, 2), 256>>>(x);

    epilogue_kernel<<<4096, 256>>>(bb);
    gram_kernel<<<BB * NCH, 256>>>();

    int ws = (out_size >= TT * BB * NN + BB * NN * NN) ? 1 : 0;
    wy_scan_kernel<<<dim3(BB, 8), 64>>>(S0, out, ws);
}

// round 12
// speedup vs baseline: 1.4657x; 1.2963x over previous
#include <cuda_runtime.h>
#include <cuda_bf16.h>
#include <cstdint>
#include <cstddef>

#define TT 2048
#define BB 16
#define DIMK 1024
#define NN 64
#define NTOT 256
#define MROWS (TT*BB)
#define LC 16
#define NCH (TT/LC)

#if defined(__CUDA_ARCH__) && (__CUDA_ARCH__ >= 1000) && \
    (defined(__CUDA_ARCH_FEAT_SM103_ALL) || defined(__CUDA_ARCH_FEAT_SM100_ALL))
#define HAS_TC 1
#else
#define HAS_TC 0
#endif

__device__ __align__(128) __nv_bfloat16 g_xhi[(size_t)MROWS * DIMK];
__device__ __align__(128) __nv_bfloat16 g_xlo[(size_t)MROWS * DIMK];
__device__ __align__(128) __nv_bfloat16 g_whi[NTOT * DIMK];
__device__ __align__(128) __nv_bfloat16 g_wlo[NTOT * DIMK];
__device__ __align__(128) float scr_w[NTOT * DIMK];
__device__ __align__(128) float scr_raw[(size_t)MROWS * NTOT];
__device__ __align__(128) float scr_kk[(size_t)BB * NCH * 256];
__device__ __align__(128) float scr_kq[(size_t)BB * NCH * 256];
__device__ __align__(128) float scr_ivg[(size_t)MROWS * 64];   // 1/g per (m, n)

#define SWZ(off) ((off) ^ (((off) >> 3) & 0x70))

__device__ __forceinline__ void cp_async16(void *smem_dst, const void *gsrc) {
    unsigned sa = (unsigned)__cvta_generic_to_shared(smem_dst);
    asm volatile("cp.async.ca.shared.global [%0], [%1], 16;" :: "r"(sa), "l"(gsrc));
}
__device__ __forceinline__ unsigned long long pack2(float x, float y) {
    unsigned long long r; asm("mov.b64 %0, {%1, %2};" : "=l"(r) : "f"(x), "f"(y)); return r;
}
__device__ __forceinline__ void unpack2(unsigned long long v, float &x, float &y) {
    asm("mov.b64 {%0, %1}, %2;" : "=f"(x), "=f"(y) : "l"(v));
}
__device__ __forceinline__ void ffma2(unsigned long long &c, unsigned long long a, unsigned long long b) {
    asm("fma.rn.f32x2 %0, %1, %2, %0;" : "+l"(c) : "l"(a), "l"(b));
}
__device__ __forceinline__ void split4(float4 v, uint2 &uh, uint2 &ul) {
    __nv_bfloat16 h0 = __float2bfloat16(v.x), h1 = __float2bfloat16(v.y);
    __nv_bfloat16 h2 = __float2bfloat16(v.z), h3 = __float2bfloat16(v.w);
    __nv_bfloat16 l0 = __float2bfloat16(v.x - __bfloat162float(h0));
    __nv_bfloat16 l1 = __float2bfloat16(v.y - __bfloat162float(h1));
    __nv_bfloat16 l2 = __float2bfloat16(v.z - __bfloat162float(h2));
    __nv_bfloat16 l3 = __float2bfloat16(v.w - __bfloat162float(h3));
    uh.x = ((uint32_t)__bfloat16_as_ushort(h1) << 16) | __bfloat16_as_ushort(h0);
    uh.y = ((uint32_t)__bfloat16_as_ushort(h3) << 16) | __bfloat16_as_ushort(h2);
    ul.x = ((uint32_t)__bfloat16_as_ushort(l1) << 16) | __bfloat16_as_ushort(l0);
    ul.y = ((uint32_t)__bfloat16_as_ushort(l3) << 16) | __bfloat16_as_ushort(l2);
}

#if HAS_TC
__device__ __forceinline__ uint64_t make_desc(uint32_t a) {
    return ((uint64_t)2 << 61) | ((uint64_t)1 << 46) | ((uint64_t)64 << 32) |
           ((uint64_t)1 << 16) | ((a >> 4) & 0x3FFF);
}
__device__ __forceinline__ void mbar_init(uint32_t addr, uint32_t cnt) {
    asm volatile("mbarrier.init.shared.b64 [%0], %1;" :: "r"(addr), "r"(cnt) : "memory");
}
__device__ __forceinline__ void mbar_wait(uint32_t addr, uint32_t parity) {
    uint32_t done;
    asm volatile("{\n\t.reg .pred p;\n\t"
        "mbarrier.try_wait.parity.acquire.cta.shared::cta.b64 p, [%1], %2;\n\t"
        "selp.b32 %0, 1, 0, p;\n\t}" : "=r"(done) : "r"(addr), "r"(parity) : "memory");
    if (!done) {
        asm volatile("{\n\t.reg .pred P1;\n\t"
            "WL_%=:\n\t"
            "mbarrier.try_wait.parity.acquire.cta.shared::cta.b64 P1, [%0], %1, 0x989680;\n\t"
            "@P1 bra.uni WD_%=;\n\tbra.uni WL_%=;\n\tWD_%=:\n\t}"
            :: "r"(addr), "r"(parity) : "memory");
    }
}
__device__ __forceinline__ void mma_f16_ss(uint32_t d, uint64_t a, uint64_t b,
                                           uint32_t idesc, uint32_t en) {
    asm volatile("{\n\t.reg .pred p;\n\t"
        "setp.ne.u32 p, %5, 0;\n\t"
        "tcgen05.mma.cta_group::1.kind::f16 [%0], %1, %2, %3, {%4, %4, %4, %4}, p;\n\t}"
        :: "r"(d), "l"(a), "l"(b), "r"(idesc), "r"(0u), "r"(en) : "memory");
}
#endif

__global__ void copyw_kernel(const float *__restrict__ wk, const float *__restrict__ wv,
                             const float *__restrict__ wq, const float *__restrict__ wb) {
#if !HAS_TC
    int i = blockIdx.x * 256 + threadIdx.x;
    int sel = i >> 16, off = i & 65535;
    const float *src = (sel == 0) ? wk : (sel == 1) ? wv : (sel == 2) ? wq : wb;
    scr_w[i] = src[off];
#endif
}

__global__ void convw_kernel(const float *__restrict__ wk, const float *__restrict__ wv,
                             const float *__restrict__ wq, const float *__restrict__ wb) {
#if HAS_TC
    int g = blockIdx.x * 256 + threadIdx.x;
    int i4 = g * 4;
    int n = i4 >> 10, k = i4 & 1023;
    int sel = n >> 6, r = n & 63;
    const float *src = (sel == 0) ? wk : (sel == 1) ? wv : (sel == 2) ? wq : wb;
    float4 v = *(const float4 *)(src + (size_t)r * DIMK + k);
    uint2 uh, ul; split4(v, uh, ul);
    *(uint2 *)(g_whi + i4) = uh; *(uint2 *)(g_wlo + i4) = ul;
#endif
}

__global__ void convx_kernel(const float *__restrict__ x) {
#if HAS_TC
    size_t i4 = ((size_t)blockIdx.x * 256 + threadIdx.x) * 4;
    float4 v = *(const float4 *)(x + i4);
    uint2 uh, ul; split4(v, uh, ul);
    *(uint2 *)(g_xhi + i4) = uh; *(uint2 *)(g_xlo + i4) = ul;
#endif
}

__global__ __launch_bounds__(256, 2) void fb_gemm_kernel(const float *__restrict__ X) {
#if !HAS_TC
    __shared__ __align__(16) float As[16 * 128];
    __shared__ __align__(16) float Bs[16 * 128];
    const int tid = threadIdx.x;
    const int m0 = blockIdx.x * 128, n0 = blockIdx.y * 128;
    const int tm = tid >> 4, tn = tid & 15;
    unsigned long long acc[4][8];
#pragma unroll
    for (int i = 0; i < 4; i++)
#pragma unroll
        for (int j = 0; j < 8; j++) acc[i][j] = 0ull;
    const int u0 = tid * 2;
    const int arow0 = u0 >> 2, ac40 = u0 & 3;
    const int arow1 = (u0 + 1) >> 2, ac41 = (u0 + 1) & 3;
    const float *Xb = X + (size_t)m0 * DIMK;
    const float *Wb = scr_w + (size_t)n0 * DIMK;
    for (int kt = 0; kt < DIMK; kt += 16) {
        float4 a0 = *(const float4 *)(Xb + (size_t)arow0 * DIMK + kt + ac40 * 4);
        float4 a1 = *(const float4 *)(Xb + (size_t)arow1 * DIMK + kt + ac41 * 4);
        float4 b0 = *(const float4 *)(Wb + (size_t)arow0 * DIMK + kt + ac40 * 4);
        float4 b1 = *(const float4 *)(Wb + (size_t)arow1 * DIMK + kt + ac41 * 4);
        __syncthreads();
        {
            int k0 = ac40 * 4, k1 = ac41 * 4;
            As[(k0+0)*128+arow0]=a0.x; As[(k0+1)*128+arow0]=a0.y;
            As[(k0+2)*128+arow0]=a0.z; As[(k0+3)*128+arow0]=a0.w;
            As[(k1+0)*128+arow1]=a1.x; As[(k1+1)*128+arow1]=a1.y;
            As[(k1+2)*128+arow1]=a1.z; As[(k1+3)*128+arow1]=a1.w;
            Bs[(k0+0)*128+arow0]=b0.x; Bs[(k0+1)*128+arow0]=b0.y;
            Bs[(k0+2)*128+arow0]=b0.z; Bs[(k0+3)*128+arow0]=b0.w;
            Bs[(k1+0)*128+arow1]=b1.x; Bs[(k1+1)*128+arow1]=b1.y;
            Bs[(k1+2)*128+arow1]=b1.z; Bs[(k1+3)*128+arow1]=b1.w;
        }
        __syncthreads();
#pragma unroll
        for (int k = 0; k < 16; k++) {
            const ulonglong2 *pa = (const ulonglong2 *)&As[k * 128 + tm * 8];
            ulonglong2 av0 = pa[0], av1 = pa[1];
            float4 bv0 = *(const float4 *)&Bs[k * 128 + tn * 8];
            float4 bv1 = *(const float4 *)&Bs[k * 128 + tn * 8 + 4];
            unsigned long long ap[4] = {av0.x, av0.y, av1.x, av1.y};
            unsigned long long bbx[8];
            bbx[0]=pack2(bv0.x,bv0.x); bbx[1]=pack2(bv0.y,bv0.y);
            bbx[2]=pack2(bv0.z,bv0.z); bbx[3]=pack2(bv0.w,bv0.w);
            bbx[4]=pack2(bv1.x,bv1.x); bbx[5]=pack2(bv1.y,bv1.y);
            bbx[6]=pack2(bv1.z,bv1.z); bbx[7]=pack2(bv1.w,bv1.w);
#pragma unroll
            for (int mp = 0; mp < 4; mp++)
#pragma unroll
                for (int n = 0; n < 8; n++) ffma2(acc[mp][n], ap[mp], bbx[n]);
        }
    }
#pragma unroll
    for (int mp = 0; mp < 4; mp++) {
        float lo[8], hi[8];
#pragma unroll
        for (int n = 0; n < 8; n++) unpack2(acc[mp][n], lo[n], hi[n]);
        int mA = m0 + tm * 8 + mp * 2;
        float *outp = scr_raw + (size_t)mA * NTOT + n0 + tn * 8;
        *(float4 *)(outp)            = make_float4(lo[0], lo[1], lo[2], lo[3]);
        *(float4 *)(outp + 4)        = make_float4(lo[4], lo[5], lo[6], lo[7]);
        *(float4 *)(outp + NTOT)     = make_float4(hi[0], hi[1], hi[2], hi[3]);
        *(float4 *)(outp + NTOT + 4) = make_float4(hi[4], hi[5], hi[6], hi[7]);
    }
#endif
}

#define GK 64
#define NKC (DIMK / GK)
#define A_BYTES (128 * 128)
#define B_BYTES (256 * 128)
#define ST_BYTES (2 * A_BYTES + 2 * B_BYTES)
#define SMEM_GEMM_TOTAL (1024 + 2 * ST_BYTES)
#define G_IDESC ((1u << 4) | (1u << 7) | (1u << 10) | ((NTOT / 8) << 17) | ((128 / 16) << 24))

extern __shared__ __align__(1024) char gsm[];

#if HAS_TC
__device__ __forceinline__ void g_load_chunk(char *stp, int m0, int kc, int tid) {
    const char *xh = (const char *)(g_xhi + (size_t)m0 * DIMK + kc * GK);
    const char *xl = (const char *)(g_xlo + (size_t)m0 * DIMK + kc * GK);
#pragma unroll
    for (int i = 0; i < 8; i++) {
        int idx = tid + i * 128;
        int row = idx >> 3, gr = idx & 7;
        uint32_t sw = SWZ(row * 128 + gr * 16);
        size_t gof = (size_t)row * (DIMK * 2) + gr * 16;
        cp_async16(stp + sw, xh + gof);
        cp_async16(stp + A_BYTES + sw, xl + gof);
    }
    const char *wh = (const char *)(g_whi + kc * GK);
    const char *wl = (const char *)(g_wlo + kc * GK);
#pragma unroll
    for (int i = 0; i < 16; i++) {
        int idx = tid + i * 128;
        int row = idx >> 3, gr = idx & 7;
        uint32_t sw = SWZ(row * 128 + gr * 16);
        size_t gof = (size_t)row * (DIMK * 2) + gr * 16;
        cp_async16(stp + 2 * A_BYTES + sw, wh + gof);
        cp_async16(stp + 2 * A_BYTES + B_BYTES + sw, wl + gof);
    }
}
#endif

__global__ __launch_bounds__(128, 1)
void mma_gemm_kernel() {
#if HAS_TC
    const int tid = threadIdx.x, wid = tid >> 5, lid = tid & 31;
    const int m0 = blockIdx.x * 128;
    uint32_t sbase = (uint32_t)__cvta_generic_to_shared(gsm);
    if (wid == 0) {
        asm volatile("tcgen05.alloc.cta_group::1.sync.aligned.shared::cta.b32 [%0], %1;"
                     :: "r"(sbase), "r"(256u) : "memory");
        asm volatile("tcgen05.relinquish_alloc_permit.cta_group::1.sync.aligned;");
    }
    if (tid == 0) { mbar_init(sbase + 16, 1); mbar_init(sbase + 24, 1); }
    __syncthreads();
    uint32_t tmem;
    asm volatile("ld.shared.b32 %0, [%1];" : "=r"(tmem) : "r"(sbase));
    g_load_chunk(gsm + 1024, m0, 0, tid);
    asm volatile("cp.async.commit_group;");
    g_load_chunk(gsm + 1024 + ST_BYTES, m0, 1, tid);
    asm volatile("cp.async.commit_group;");
    int ph0 = 0, ph1 = 0;
    for (int c = 0; c < NKC; c++) {
        int s = c & 1;
        char *stp = gsm + 1024 + s * ST_BYTES;
        uint32_t sa = sbase + 1024 + s * ST_BYTES;
        if (c < NKC - 1) asm volatile("cp.async.wait_group 1;" ::: "memory");
        else             asm volatile("cp.async.wait_group 0;" ::: "memory");
        __syncthreads();
        if (tid == 0) {
            asm volatile("fence.proxy.async.shared::cta;" ::: "memory");
            uint64_t ahi = make_desc(sa), alo = make_desc(sa + A_BYTES);
            uint64_t bhi = make_desc(sa + 2 * A_BYTES), blo = make_desc(sa + 2 * A_BYTES + B_BYTES);
#pragma unroll
            for (int k = 0; k < 4; k++)
                mma_f16_ss(tmem, ahi + k * 2, bhi + k * 2, G_IDESC, !(c == 0 && k == 0));
#pragma unroll
            for (int k = 0; k < 4; k++)
                mma_f16_ss(tmem, ahi + k * 2, blo + k * 2, G_IDESC, 1u);
#pragma unroll
            for (int k = 0; k < 4; k++)
                mma_f16_ss(tmem, alo + k * 2, bhi + k * 2, G_IDESC, 1u);
            asm volatile(
                "tcgen05.commit.cta_group::1.mbarrier::arrive::one.shared::cluster.b64 [%0];"
                :: "r"(sbase + 16 + s * 8) : "memory");
        }
        if (c + 2 < NKC) {
            if (s == 0) { mbar_wait(sbase + 16, ph0 & 1); ph0++; }
            else        { mbar_wait(sbase + 24, ph1 & 1); ph1++; }
            g_load_chunk(stp, m0, c + 2, tid);
            asm volatile("cp.async.commit_group;");
        }
    }
    mbar_wait(sbase + 16, ph0 & 1);
    mbar_wait(sbase + 24, ph1 & 1);
    asm volatile("tcgen05.fence::after_thread_sync;" ::: "memory");
    float *orow = scr_raw + (size_t)(m0 + wid * 32 + lid) * NTOT;
#pragma unroll 1
    for (int cb = 0; cb < 8; cb++) {
        uint32_t r[32];
        asm volatile(
            "tcgen05.ld.sync.aligned.32x32b.x32.b32 "
            "{%0, %1, %2, %3, %4, %5, %6, %7, %8, %9, %10, %11, %12, %13, %14, %15, "
            " %16, %17, %18, %19, %20, %21, %22, %23, %24, %25, %26, %27, %28, %29, %30, %31}, [%32];"
            : "=r"(r[0]),"=r"(r[1]),"=r"(r[2]),"=r"(r[3]),"=r"(r[4]),"=r"(r[5]),
              "=r"(r[6]),"=r"(r[7]),"=r"(r[8]),"=r"(r[9]),"=r"(r[10]),"=r"(r[11]),
              "=r"(r[12]),"=r"(r[13]),"=r"(r[14]),"=r"(r[15]),"=r"(r[16]),"=r"(r[17]),
              "=r"(r[18]),"=r"(r[19]),"=r"(r[20]),"=r"(r[21]),"=r"(r[22]),"=r"(r[23]),
              "=r"(r[24]),"=r"(r[25]),"=r"(r[26]),"=r"(r[27]),"=r"(r[28]),"=r"(r[29]),
              "=r"(r[30]),"=r"(r[31])
            : "r"(tmem + cb * 32));
        asm volatile("tcgen05.wait::ld.sync.aligned;" ::: "memory");
        float4 *o4 = (float4 *)(orow + cb * 32);
#pragma unroll
        for (int i = 0; i < 8; i++)
            o4[i] = make_float4(__uint_as_float(r[i*4]), __uint_as_float(r[i*4+1]),
                                __uint_as_float(r[i*4+2]), __uint_as_float(r[i*4+3]));
    }
    __syncthreads();
    if (wid == 0)
        asm volatile("tcgen05.dealloc.cta_group::1.sync.aligned.b32 %0, %1;"
                     :: "r"(tmem), "r"(256u));
#endif
}

// ===== epilogue: kn normalize + gate + 1/g (exact: 1/sigmoid = 1+exp(-x)) =====
__global__ void epilogue_kernel(const float *__restrict__ b_beta) {
    int warp = (blockIdx.x * blockDim.x + threadIdx.x) >> 5;
    int lane = threadIdx.x & 31;
    if (warp >= MROWS) return;
    float *row = scr_raw + (size_t)warp * NTOT;
    int i0 = lane * 2;
    float2 kv = *(float2 *)(row + i0);
    float2 bt = *(float2 *)(row + 192 + i0);
    float nk = kv.x * kv.x + kv.y * kv.y;
#pragma unroll
    for (int off = 16; off; off >>= 1) nk += __shfl_xor_sync(0xffffffffu, nk, off);
    float inv = 1.0f / (sqrtf(nk) + 1e-6f);
    float ex = __expf(-(bt.x + b_beta[i0]));
    float ey = __expf(-(bt.y + b_beta[i0 + 1]));
    float gx = 1.0f / (1.0f + ex);
    float gy = 1.0f / (1.0f + ey);
    *(float2 *)(row + i0)       = make_float2(kv.x * inv, kv.y * inv);
    *(float2 *)(row + 192 + i0) = make_float2(gx, gy);
    *(float2 *)(scr_ivg + (size_t)warp * 64 + i0) = make_float2(1.0f + ex, 1.0f + ey);
}

// ===== gram: per (b,chunk) KK[j][t]=kn_j.kn_t, KQ[j][t]=kn_j.q_t =====
__global__ __launch_bounds__(256) void gram_kernel() {
    __shared__ __align__(16) float kn_s[16 * 68], q_s[16 * 68];
    const int gb = blockIdx.x;
    const int ch = gb >> 4, b = gb & 15;
    const int tid = threadIdx.x;
    {
        int t = tid >> 4, c4 = tid & 15;
        size_t m = (size_t)(ch * 16 + t) * BB + b;
        float4 a = *(const float4 *)(scr_raw + m * NTOT + c4 * 4);
        float4 c = *(const float4 *)(scr_raw + m * NTOT + 128 + c4 * 4);
        *(float4 *)(kn_s + t * 68 + c4 * 4) = a;
        *(float4 *)(q_s  + t * 68 + c4 * 4) = c;
    }
    __syncthreads();
    const int j = tid >> 4, t = tid & 15;
    float ak = 0.f, aq = 0.f;
#pragma unroll
    for (int c4 = 0; c4 < 16; c4++) {
        float4 a  = *(const float4 *)(kn_s + j * 68 + c4 * 4);
        float4 bk = *(const float4 *)(kn_s + t * 68 + c4 * 4);
        float4 bq = *(const float4 *)(q_s  + t * 68 + c4 * 4);
        ak = fmaf(a.x,bk.x,fmaf(a.y,bk.y,fmaf(a.z,bk.z,fmaf(a.w,bk.w,ak))));
        aq = fmaf(a.x,bq.x,fmaf(a.y,bq.y,fmaf(a.z,bq.z,fmaf(a.w,bq.w,aq))));
    }
    scr_kk[(size_t)gb * 256 + j * 16 + t] = ak;
    scr_kq[(size_t)gb * 256 + j * 16 + t] = aq;
}

// ===== WY chunked scan v2: 128 threads, c' = delta/G parametrization =====
struct __align__(16) ScanBuf {
    float kn[16 * 68], q[16 * 68];
    float v[16 * 8], g[16 * 8], ig[16 * 8];
    float kk[256], kq[256];
};
#define WY_UNITS 736   // 256 kn + 256 q + 32 v + 32 g + 32 ig + 64 kk + 64 kq (float4)

__device__ __forceinline__ void wy_issue(ScanBuf *sb, int ch, int b, int r0, int tid) {
#pragma unroll
    for (int i = 0; i < 6; i++) {
        int u = tid + i * 128;
        if (u >= WY_UNITS) break;
        if (u < 512) {
            int t = (u & 255) >> 4, f4 = u & 15;
            size_t m = (size_t)(ch * 16 + t) * BB + b;
            if (u < 256) cp_async16(sb->kn + t * 68 + f4 * 4, scr_raw + m * NTOT + f4 * 4);
            else         cp_async16(sb->q  + t * 68 + f4 * 4, scr_raw + m * NTOT + 128 + f4 * 4);
        } else if (u < 608) {
            int w = u - 512;
            int t = (w & 31) >> 1, part = w & 1;
            size_t m = (size_t)(ch * 16 + t) * BB + b;
            if (w < 32)       cp_async16(sb->v  + t * 8 + part * 4, scr_raw + m * NTOT + 64 + r0 + part * 4);
            else if (w < 64)  cp_async16(sb->g  + t * 8 + part * 4, scr_raw + m * NTOT + 192 + r0 + part * 4);
            else              cp_async16(sb->ig + t * 8 + part * 4, scr_ivg + m * 64 + r0 + part * 4);
        } else {
            int w = u - 608;
            size_t base = (size_t)(ch * 16 + b) * 256 + (w & 63) * 4;
            if (w < 64) cp_async16(sb->kk + (w & 63) * 4, scr_kk + base);
            else        cp_async16(sb->kq + (w & 63) * 4, scr_kq + base);
        }
    }
}

__global__ __launch_bounds__(128) void wy_scan_kernel(const float *__restrict__ S0,
                                                      float *__restrict__ out,
                                                      int write_sfinal) {
    __shared__ ScanBuf sb[2];
    __shared__ __align__(16) float S_s[8 * 68];
    __shared__ __align__(16) float A_s[16 * 8], Aq_s[16 * 8];
    __shared__ float cp_s[8 * 17];      // c' per (row, j)
    __shared__ float Gs_s[16 * 8];      // G_t per (t, row)
    __shared__ float sh_out[16 * 8];

    const int b = blockIdx.x, r0 = blockIdx.y * 8;
    const int tid = threadIdx.x;
    const int rl4 = tid >> 4;           // 0..7 (row for 16-wide splits)
    const int c16 = tid & 15;           // 0..15

    // init state: one float4 per thread
    {
        const float *sp = S0 + ((size_t)b * 64 + r0 + rl4) * 64 + c16 * 4;
        *(float4 *)(S_s + rl4 * 68 + c16 * 4) = *(const float4 *)sp;
    }

    wy_issue(&sb[0], 0, b, r0, tid);
    asm volatile("cp.async.commit_group;");

    for (int ch = 0; ch < NCH; ch++) {
        const int pb = ch & 1;
        ScanBuf *B = &sb[pb];
        if (ch + 1 < NCH) {
            wy_issue(&sb[pb ^ 1], ch + 1, b, r0, tid);
            asm volatile("cp.async.commit_group;");
            asm volatile("cp.async.wait_group 1;");
        } else {
            asm volatile("cp.async.wait_group 0;");
        }
        __syncthreads();

        // ph1: thread (rl4, t=c16): A[t][rl4] = S_row . kn_t ; Aq = S_row . q_t
        {
            const int t = c16;
            float a0 = 0.f, b0 = 0.f;
#pragma unroll
            for (int s4 = 0; s4 < 16; s4++) {
                float4 sv = *(const float4 *)(S_s + rl4 * 68 + s4 * 4);
                float4 kv = *(const float4 *)(B->kn + t * 68 + s4 * 4);
                float4 qv = *(const float4 *)(B->q  + t * 68 + s4 * 4);
                a0 = fmaf(sv.x,kv.x,fmaf(sv.y,kv.y,fmaf(sv.z,kv.z,fmaf(sv.w,kv.w,a0))));
                b0 = fmaf(sv.x,qv.x,fmaf(sv.y,qv.y,fmaf(sv.z,qv.z,fmaf(sv.w,qv.w,b0))));
            }
            A_s [t * 8 + rl4] = a0;
            Aq_s[t * 8 + rl4] = b0;
        }
        __syncthreads();

        // ph2: serial c' recursion, threads 0..7 = rows. Column-sweep fan-out.
        if (tid < 8) {
            const int row = tid;
            float acc[16];
#pragma unroll
            for (int u = 0; u < 16; u++) acc[u] = 0.f;
            float cp[16];
            float G = 1.0f, iG = 1.0f;
#pragma unroll
            for (int t = 0; t < 16; t++) {
                float a  = A_s[t * 8 + row];
                float vt = B->v[t * 8 + row];
                float gt = B->g[t * 8 + row];
                float it = B->ig[t * 8 + row];
                float delta = vt - G * (a + acc[t]);   // G = G_{t-1}
                G *= gt;                                // G_t
                iG *= it;                               // 1/G_t
                float ct = delta * iG;
                cp[t] = ct;
                Gs_s[t * 8 + row] = G;
#pragma unroll
                for (int u = t + 1; u < 16; u++)
                    acc[u] = fmaf(ct, B->kk[t * 16 + u], acc[u]);
            }
#pragma unroll
            for (int j = 0; j < 16; j++) cp_s[row * 17 + j] = cp[j];
        }
        __syncthreads();

        // ph2c: outputs, thread (row=rl4... use row = tid>>4, t = tid&15)
        {
            const int row = rl4, t = c16;
            float sum = Aq_s[t * 8 + row];
            for (int j = 0; j <= t; j++)
                sum = fmaf(cp_s[row * 17 + j], B->kq[j * 16 + t], sum);
            float Sq = Gs_s[t * 8 + row] * sum;
            float sg = 1.0f / (1.0f + __expf(-Sq));
            sh_out[t * 8 + row] = Sq * Sq * sg;
        }

        // ph3: S = G_L * (S + sum_j c'_j kn_j); thread (rl4, c16): one float4
        {
            float gl = Gs_s[15 * 8 + rl4];
            float4 s0 = *(const float4 *)(S_s + rl4 * 68 + c16 * 4);
#pragma unroll
            for (int j = 0; j < 16; j++) {
                float cj = cp_s[rl4 * 17 + j];
                float4 kv = *(const float4 *)(B->kn + j * 68 + c16 * 4);
                s0.x = fmaf(cj, kv.x, s0.x); s0.y = fmaf(cj, kv.y, s0.y);
                s0.z = fmaf(cj, kv.z, s0.z); s0.w = fmaf(cj, kv.w, s0.w);
            }
            s0.x *= gl; s0.y *= gl; s0.z *= gl; s0.w *= gl;
            *(float4 *)(S_s + rl4 * 68 + c16 * 4) = s0;
        }
        __syncthreads();

        // ph4: flush outputs (128 floats, 1/thread)
        {
            const int t = tid >> 3, r = tid & 7;
            out[(size_t)(ch * 16 + t) * (BB * NN) + b * NN + r0 + r] = sh_out[t * 8 + r];
        }
    }

    if (write_sfinal) {
        float *sf = out + (size_t)TT * BB * NN + ((size_t)b * 64 + r0 + rl4) * 64 + c16 * 4;
        *(float4 *)sf = *(const float4 *)(S_s + rl4 * 68 + c16 * 4);
    }
}

// ======================================================================
extern "C" void kernel_launch(void *const *d_in, const int *in_sizes, int n_in,
                              void *d_out, int out_size) {
    const float *x  = (const float *)d_in[0];
    const float *S0 = (const float *)d_in[1];
    const float *Wk = (const float *)d_in[2];
    const float *Wv = (const float *)d_in[3];
    const float *Wq = (const float *)d_in[4];
    const float *Wb = (const float *)d_in[5];
    const float *bb = (const float *)d_in[6];
    float *out = (float *)d_out;

    cudaFuncSetAttribute(mma_gemm_kernel, cudaFuncAttributeMaxDynamicSharedMemorySize,
                         SMEM_GEMM_TOTAL);

    copyw_kernel<<<1024, 256>>>(Wk, Wv, Wq, Wb);
    convw_kernel<<<256, 256>>>(Wk, Wv, Wq, Wb);
    convx_kernel<<<32768, 256>>>(x);

    mma_gemm_kernel<<<MROWS / 128, 128, SMEM_GEMM_TOTAL>>>();
    fb_gemm_kernel<<<dim3(MROWS / 128, 2), 256>>>(x);

    epilogue_kernel<<<4096, 256>>>(bb);
    gram_kernel<<<BB * NCH, 256>>>();

    int ws = (out_size >= TT * BB * NN + BB * NN * NN) ? 1 : 0;
    wy_scan_kernel<<<dim3(BB, 8), 128>>>(S0, out, ws);
}

// round 13
// speedup vs baseline: 1.4658x; 1.0001x over previous
#include <cuda_runtime.h>
#include <cuda_bf16.h>
#include <cstdint>
#include <cstddef>

#define TT 2048
#define BB 16
#define DIMK 1024
#define NN 64
#define NTOT 256
#define MROWS (TT*BB)
#define LC 16
#define NCH (TT/LC)

#if defined(__CUDA_ARCH__) && (__CUDA_ARCH__ >= 1000) && \
    (defined(__CUDA_ARCH_FEAT_SM103_ALL) || defined(__CUDA_ARCH_FEAT_SM100_ALL))
#define HAS_TC 1
#else
#define HAS_TC 0
#endif

__device__ __align__(128) __nv_bfloat16 g_xhi[(size_t)MROWS * DIMK];
__device__ __align__(128) __nv_bfloat16 g_xlo[(size_t)MROWS * DIMK];
__device__ __align__(128) __nv_bfloat16 g_whi[NTOT * DIMK];
__device__ __align__(128) __nv_bfloat16 g_wlo[NTOT * DIMK];
__device__ __align__(128) float scr_w[NTOT * DIMK];
__device__ __align__(128) float scr_raw[(size_t)MROWS * NTOT];
__device__ __align__(128) float scr_kk[(size_t)BB * NCH * 256];
__device__ __align__(128) float scr_kq[(size_t)BB * NCH * 256];
__device__ __align__(128) float scr_ivg[(size_t)MROWS * 64];   // 1/g per (m, n)

#define SWZ(off) ((off) ^ (((off) >> 3) & 0x70))

__device__ __forceinline__ void cp_async16(void *smem_dst, const void *gsrc) {
    unsigned sa = (unsigned)__cvta_generic_to_shared(smem_dst);
    asm volatile("cp.async.ca.shared.global [%0], [%1], 16;" :: "r"(sa), "l"(gsrc));
}
__device__ __forceinline__ void cp_async4(void *smem_dst, const void *gsrc) {
    unsigned sa = (unsigned)__cvta_generic_to_shared(smem_dst);
    asm volatile("cp.async.ca.shared.global [%0], [%1], 4;" :: "r"(sa), "l"(gsrc));
}
__device__ __forceinline__ unsigned long long pack2(float x, float y) {
    unsigned long long r; asm("mov.b64 %0, {%1, %2};" : "=l"(r) : "f"(x), "f"(y)); return r;
}
__device__ __forceinline__ void unpack2(unsigned long long v, float &x, float &y) {
    asm("mov.b64 {%0, %1}, %2;" : "=f"(x), "=f"(y) : "l"(v));
}
__device__ __forceinline__ void ffma2(unsigned long long &c, unsigned long long a, unsigned long long b) {
    asm("fma.rn.f32x2 %0, %1, %2, %0;" : "+l"(c) : "l"(a), "l"(b));
}
__device__ __forceinline__ void split4(float4 v, uint2 &uh, uint2 &ul) {
    __nv_bfloat16 h0 = __float2bfloat16(v.x), h1 = __float2bfloat16(v.y);
    __nv_bfloat16 h2 = __float2bfloat16(v.z), h3 = __float2bfloat16(v.w);
    __nv_bfloat16 l0 = __float2bfloat16(v.x - __bfloat162float(h0));
    __nv_bfloat16 l1 = __float2bfloat16(v.y - __bfloat162float(h1));
    __nv_bfloat16 l2 = __float2bfloat16(v.z - __bfloat162float(h2));
    __nv_bfloat16 l3 = __float2bfloat16(v.w - __bfloat162float(h3));
    uh.x = ((uint32_t)__bfloat16_as_ushort(h1) << 16) | __bfloat16_as_ushort(h0);
    uh.y = ((uint32_t)__bfloat16_as_ushort(h3) << 16) | __bfloat16_as_ushort(h2);
    ul.x = ((uint32_t)__bfloat16_as_ushort(l1) << 16) | __bfloat16_as_ushort(l0);
    ul.y = ((uint32_t)__bfloat16_as_ushort(l3) << 16) | __bfloat16_as_ushort(l2);
}

#if HAS_TC
__device__ __forceinline__ uint64_t make_desc(uint32_t a) {
    return ((uint64_t)2 << 61) | ((uint64_t)1 << 46) | ((uint64_t)64 << 32) |
           ((uint64_t)1 << 16) | ((a >> 4) & 0x3FFF);
}
__device__ __forceinline__ void mbar_init(uint32_t addr, uint32_t cnt) {
    asm volatile("mbarrier.init.shared.b64 [%0], %1;" :: "r"(addr), "r"(cnt) : "memory");
}
__device__ __forceinline__ void mbar_wait(uint32_t addr, uint32_t parity) {
    uint32_t done;
    asm volatile("{\n\t.reg .pred p;\n\t"
        "mbarrier.try_wait.parity.acquire.cta.shared::cta.b64 p, [%1], %2;\n\t"
        "selp.b32 %0, 1, 0, p;\n\t}" : "=r"(done) : "r"(addr), "r"(parity) : "memory");
    if (!done) {
        asm volatile("{\n\t.reg .pred P1;\n\t"
            "WL_%=:\n\t"
            "mbarrier.try_wait.parity.acquire.cta.shared::cta.b64 P1, [%0], %1, 0x989680;\n\t"
            "@P1 bra.uni WD_%=;\n\tbra.uni WL_%=;\n\tWD_%=:\n\t}"
            :: "r"(addr), "r"(parity) : "memory");
    }
}
__device__ __forceinline__ void mma_f16_ss(uint32_t d, uint64_t a, uint64_t b,
                                           uint32_t idesc, uint32_t en) {
    asm volatile("{\n\t.reg .pred p;\n\t"
        "setp.ne.u32 p, %5, 0;\n\t"
        "tcgen05.mma.cta_group::1.kind::f16 [%0], %1, %2, %3, {%4, %4, %4, %4}, p;\n\t}"
        :: "r"(d), "l"(a), "l"(b), "r"(idesc), "r"(0u), "r"(en) : "memory");
}
#endif

__global__ void copyw_kernel(const float *__restrict__ wk, const float *__restrict__ wv,
                             const float *__restrict__ wq, const float *__restrict__ wb) {
#if !HAS_TC
    int i = blockIdx.x * 256 + threadIdx.x;
    int sel = i >> 16, off = i & 65535;
    const float *src = (sel == 0) ? wk : (sel == 1) ? wv : (sel == 2) ? wq : wb;
    scr_w[i] = src[off];
#endif
}

__global__ void convw_kernel(const float *__restrict__ wk, const float *__restrict__ wv,
                             const float *__restrict__ wq, const float *__restrict__ wb) {
#if HAS_TC
    int g = blockIdx.x * 256 + threadIdx.x;
    int i4 = g * 4;
    int n = i4 >> 10, k = i4 & 1023;
    int sel = n >> 6, r = n & 63;
    const float *src = (sel == 0) ? wk : (sel == 1) ? wv : (sel == 2) ? wq : wb;
    float4 v = *(const float4 *)(src + (size_t)r * DIMK + k);
    uint2 uh, ul; split4(v, uh, ul);
    *(uint2 *)(g_whi + i4) = uh; *(uint2 *)(g_wlo + i4) = ul;
#endif
}

__global__ void convx_kernel(const float *__restrict__ x) {
#if HAS_TC
    size_t i4 = ((size_t)blockIdx.x * 256 + threadIdx.x) * 4;
    float4 v = *(const float4 *)(x + i4);
    uint2 uh, ul; split4(v, uh, ul);
    *(uint2 *)(g_xhi + i4) = uh; *(uint2 *)(g_xlo + i4) = ul;
#endif
}

__global__ __launch_bounds__(256, 2) void fb_gemm_kernel(const float *__restrict__ X) {
#if !HAS_TC
    __shared__ __align__(16) float As[16 * 128];
    __shared__ __align__(16) float Bs[16 * 128];
    const int tid = threadIdx.x;
    const int m0 = blockIdx.x * 128, n0 = blockIdx.y * 128;
    const int tm = tid >> 4, tn = tid & 15;
    unsigned long long acc[4][8];
#pragma unroll
    for (int i = 0; i < 4; i++)
#pragma unroll
        for (int j = 0; j < 8; j++) acc[i][j] = 0ull;
    const int u0 = tid * 2;
    const int arow0 = u0 >> 2, ac40 = u0 & 3;
    const int arow1 = (u0 + 1) >> 2, ac41 = (u0 + 1) & 3;
    const float *Xb = X + (size_t)m0 * DIMK;
    const float *Wb = scr_w + (size_t)n0 * DIMK;
    for (int kt = 0; kt < DIMK; kt += 16) {
        float4 a0 = *(const float4 *)(Xb + (size_t)arow0 * DIMK + kt + ac40 * 4);
        float4 a1 = *(const float4 *)(Xb + (size_t)arow1 * DIMK + kt + ac41 * 4);
        float4 b0 = *(const float4 *)(Wb + (size_t)arow0 * DIMK + kt + ac40 * 4);
        float4 b1 = *(const float4 *)(Wb + (size_t)arow1 * DIMK + kt + ac41 * 4);
        __syncthreads();
        {
            int k0 = ac40 * 4, k1 = ac41 * 4;
            As[(k0+0)*128+arow0]=a0.x; As[(k0+1)*128+arow0]=a0.y;
            As[(k0+2)*128+arow0]=a0.z; As[(k0+3)*128+arow0]=a0.w;
            As[(k1+0)*128+arow1]=a1.x; As[(k1+1)*128+arow1]=a1.y;
            As[(k1+2)*128+arow1]=a1.z; As[(k1+3)*128+arow1]=a1.w;
            Bs[(k0+0)*128+arow0]=b0.x; Bs[(k0+1)*128+arow0]=b0.y;
            Bs[(k0+2)*128+arow0]=b0.z; Bs[(k0+3)*128+arow0]=b0.w;
            Bs[(k1+0)*128+arow1]=b1.x; Bs[(k1+1)*128+arow1]=b1.y;
            Bs[(k1+2)*128+arow1]=b1.z; Bs[(k1+3)*128+arow1]=b1.w;
        }
        __syncthreads();
#pragma unroll
        for (int k = 0; k < 16; k++) {
            const ulonglong2 *pa = (const ulonglong2 *)&As[k * 128 + tm * 8];
            ulonglong2 av0 = pa[0], av1 = pa[1];
            float4 bv0 = *(const float4 *)&Bs[k * 128 + tn * 8];
            float4 bv1 = *(const float4 *)&Bs[k * 128 + tn * 8 + 4];
            unsigned long long ap[4] = {av0.x, av0.y, av1.x, av1.y};
            unsigned long long bbx[8];
            bbx[0]=pack2(bv0.x,bv0.x); bbx[1]=pack2(bv0.y,bv0.y);
            bbx[2]=pack2(bv0.z,bv0.z); bbx[3]=pack2(bv0.w,bv0.w);
            bbx[4]=pack2(bv1.x,bv1.x); bbx[5]=pack2(bv1.y,bv1.y);
            bbx[6]=pack2(bv1.z,bv1.z); bbx[7]=pack2(bv1.w,bv1.w);
#pragma unroll
            for (int mp = 0; mp < 4; mp++)
#pragma unroll
                for (int n = 0; n < 8; n++) ffma2(acc[mp][n], ap[mp], bbx[n]);
        }
    }
#pragma unroll
    for (int mp = 0; mp < 4; mp++) {
        float lo[8], hi[8];
#pragma unroll
        for (int n = 0; n < 8; n++) unpack2(acc[mp][n], lo[n], hi[n]);
        int mA = m0 + tm * 8 + mp * 2;
        float *outp = scr_raw + (size_t)mA * NTOT + n0 + tn * 8;
        *(float4 *)(outp)            = make_float4(lo[0], lo[1], lo[2], lo[3]);
        *(float4 *)(outp + 4)        = make_float4(lo[4], lo[5], lo[6], lo[7]);
        *(float4 *)(outp + NTOT)     = make_float4(hi[0], hi[1], hi[2], hi[3]);
        *(float4 *)(outp + NTOT + 4) = make_float4(hi[4], hi[5], hi[6], hi[7]);
    }
#endif
}

#define GK 64
#define NKC (DIMK / GK)
#define A_BYTES (128 * 128)
#define B_BYTES (256 * 128)
#define ST_BYTES (2 * A_BYTES + 2 * B_BYTES)
#define SMEM_GEMM_TOTAL (1024 + 2 * ST_BYTES)
#define G_IDESC ((1u << 4) | (1u << 7) | (1u << 10) | ((NTOT / 8) << 17) | ((128 / 16) << 24))

extern __shared__ __align__(1024) char gsm[];

#if HAS_TC
__device__ __forceinline__ void g_load_chunk(char *stp, int m0, int kc, int tid) {
    const char *xh = (const char *)(g_xhi + (size_t)m0 * DIMK + kc * GK);
    const char *xl = (const char *)(g_xlo + (size_t)m0 * DIMK + kc * GK);
#pragma unroll
    for (int i = 0; i < 8; i++) {
        int idx = tid + i * 128;
        int row = idx >> 3, gr = idx & 7;
        uint32_t sw = SWZ(row * 128 + gr * 16);
        size_t gof = (size_t)row * (DIMK * 2) + gr * 16;
        cp_async16(stp + sw, xh + gof);
        cp_async16(stp + A_BYTES + sw, xl + gof);
    }
    const char *wh = (const char *)(g_whi + kc * GK);
    const char *wl = (const char *)(g_wlo + kc * GK);
#pragma unroll
    for (int i = 0; i < 16; i++) {
        int idx = tid + i * 128;
        int row = idx >> 3, gr = idx & 7;
        uint32_t sw = SWZ(row * 128 + gr * 16);
        size_t gof = (size_t)row * (DIMK * 2) + gr * 16;
        cp_async16(stp + 2 * A_BYTES + sw, wh + gof);
        cp_async16(stp + 2 * A_BYTES + B_BYTES + sw, wl + gof);
    }
}
#endif

__global__ __launch_bounds__(128, 1)
void mma_gemm_kernel() {
#if HAS_TC
    const int tid = threadIdx.x, wid = tid >> 5, lid = tid & 31;
    const int m0 = blockIdx.x * 128;
    uint32_t sbase = (uint32_t)__cvta_generic_to_shared(gsm);
    if (wid == 0) {
        asm volatile("tcgen05.alloc.cta_group::1.sync.aligned.shared::cta.b32 [%0], %1;"
                     :: "r"(sbase), "r"(256u) : "memory");
        asm volatile("tcgen05.relinquish_alloc_permit.cta_group::1.sync.aligned;");
    }
    if (tid == 0) { mbar_init(sbase + 16, 1); mbar_init(sbase + 24, 1); }
    __syncthreads();
    uint32_t tmem;
    asm volatile("ld.shared.b32 %0, [%1];" : "=r"(tmem) : "r"(sbase));
    g_load_chunk(gsm + 1024, m0, 0, tid);
    asm volatile("cp.async.commit_group;");
    g_load_chunk(gsm + 1024 + ST_BYTES, m0, 1, tid);
    asm volatile("cp.async.commit_group;");
    int ph0 = 0, ph1 = 0;
    for (int c = 0; c < NKC; c++) {
        int s = c & 1;
        char *stp = gsm + 1024 + s * ST_BYTES;
        uint32_t sa = sbase + 1024 + s * ST_BYTES;
        if (c < NKC - 1) asm volatile("cp.async.wait_group 1;" ::: "memory");
        else             asm volatile("cp.async.wait_group 0;" ::: "memory");
        __syncthreads();
        if (tid == 0) {
            asm volatile("fence.proxy.async.shared::cta;" ::: "memory");
            uint64_t ahi = make_desc(sa), alo = make_desc(sa + A_BYTES);
            uint64_t bhi = make_desc(sa + 2 * A_BYTES), blo = make_desc(sa + 2 * A_BYTES + B_BYTES);
#pragma unroll
            for (int k = 0; k < 4; k++)
                mma_f16_ss(tmem, ahi + k * 2, bhi + k * 2, G_IDESC, !(c == 0 && k == 0));
#pragma unroll
            for (int k = 0; k < 4; k++)
                mma_f16_ss(tmem, ahi + k * 2, blo + k * 2, G_IDESC, 1u);
#pragma unroll
            for (int k = 0; k < 4; k++)
                mma_f16_ss(tmem, alo + k * 2, bhi + k * 2, G_IDESC, 1u);
            asm volatile(
                "tcgen05.commit.cta_group::1.mbarrier::arrive::one.shared::cluster.b64 [%0];"
                :: "r"(sbase + 16 + s * 8) : "memory");
        }
        if (c + 2 < NKC) {
            if (s == 0) { mbar_wait(sbase + 16, ph0 & 1); ph0++; }
            else        { mbar_wait(sbase + 24, ph1 & 1); ph1++; }
            g_load_chunk(stp, m0, c + 2, tid);
            asm volatile("cp.async.commit_group;");
        }
    }
    mbar_wait(sbase + 16, ph0 & 1);
    mbar_wait(sbase + 24, ph1 & 1);
    asm volatile("tcgen05.fence::after_thread_sync;" ::: "memory");
    float *orow = scr_raw + (size_t)(m0 + wid * 32 + lid) * NTOT;
#pragma unroll 1
    for (int cb = 0; cb < 8; cb++) {
        uint32_t r[32];
        asm volatile(
            "tcgen05.ld.sync.aligned.32x32b.x32.b32 "
            "{%0, %1, %2, %3, %4, %5, %6, %7, %8, %9, %10, %11, %12, %13, %14, %15, "
            " %16, %17, %18, %19, %20, %21, %22, %23, %24, %25, %26, %27, %28, %29, %30, %31}, [%32];"
            : "=r"(r[0]),"=r"(r[1]),"=r"(r[2]),"=r"(r[3]),"=r"(r[4]),"=r"(r[5]),
              "=r"(r[6]),"=r"(r[7]),"=r"(r[8]),"=r"(r[9]),"=r"(r[10]),"=r"(r[11]),
              "=r"(r[12]),"=r"(r[13]),"=r"(r[14]),"=r"(r[15]),"=r"(r[16]),"=r"(r[17]),
              "=r"(r[18]),"=r"(r[19]),"=r"(r[20]),"=r"(r[21]),"=r"(r[22]),"=r"(r[23]),
              "=r"(r[24]),"=r"(r[25]),"=r"(r[26]),"=r"(r[27]),"=r"(r[28]),"=r"(r[29]),
              "=r"(r[30]),"=r"(r[31])
            : "r"(tmem + cb * 32));
        asm volatile("tcgen05.wait::ld.sync.aligned;" ::: "memory");
        float4 *o4 = (float4 *)(orow + cb * 32);
#pragma unroll
        for (int i = 0; i < 8; i++)
            o4[i] = make_float4(__uint_as_float(r[i*4]), __uint_as_float(r[i*4+1]),
                                __uint_as_float(r[i*4+2]), __uint_as_float(r[i*4+3]));
    }
    __syncthreads();
    if (wid == 0)
        asm volatile("tcgen05.dealloc.cta_group::1.sync.aligned.b32 %0, %1;"
                     :: "r"(tmem), "r"(256u));
#endif
}

// ===== epilogue: kn normalize + gate + 1/g (exact: 1/sigmoid = 1+exp(-x)) =====
__global__ void epilogue_kernel(const float *__restrict__ b_beta) {
    int warp = (blockIdx.x * blockDim.x + threadIdx.x) >> 5;
    int lane = threadIdx.x & 31;
    if (warp >= MROWS) return;
    float *row = scr_raw + (size_t)warp * NTOT;
    int i0 = lane * 2;
    float2 kv = *(float2 *)(row + i0);
    float2 bt = *(float2 *)(row + 192 + i0);
    float nk = kv.x * kv.x + kv.y * kv.y;
#pragma unroll
    for (int off = 16; off; off >>= 1) nk += __shfl_xor_sync(0xffffffffu, nk, off);
    float inv = 1.0f / (sqrtf(nk) + 1e-6f);
    float ex = __expf(-(bt.x + b_beta[i0]));
    float ey = __expf(-(bt.y + b_beta[i0 + 1]));
    float gx = 1.0f / (1.0f + ex);
    float gy = 1.0f / (1.0f + ey);
    *(float2 *)(row + i0)       = make_float2(kv.x * inv, kv.y * inv);
    *(float2 *)(row + 192 + i0) = make_float2(gx, gy);
    *(float2 *)(scr_ivg + (size_t)warp * 64 + i0) = make_float2(1.0f + ex, 1.0f + ey);
}

// ===== gram: per (b,chunk) KK[j][t]=kn_j.kn_t, KQ[j][t]=kn_j.q_t =====
__global__ __launch_bounds__(256) void gram_kernel() {
    __shared__ __align__(16) float kn_s[16 * 68], q_s[16 * 68];
    const int gb = blockIdx.x;
    const int ch = gb >> 4, b = gb & 15;
    const int tid = threadIdx.x;
    {
        int t = tid >> 4, c4 = tid & 15;
        size_t m = (size_t)(ch * 16 + t) * BB + b;
        float4 a = *(const float4 *)(scr_raw + m * NTOT + c4 * 4);
        float4 c = *(const float4 *)(scr_raw + m * NTOT + 128 + c4 * 4);
        *(float4 *)(kn_s + t * 68 + c4 * 4) = a;
        *(float4 *)(q_s  + t * 68 + c4 * 4) = c;
    }
    __syncthreads();
    const int j = tid >> 4, t = tid & 15;
    float ak = 0.f, aq = 0.f;
#pragma unroll
    for (int c4 = 0; c4 < 16; c4++) {
        float4 a  = *(const float4 *)(kn_s + j * 68 + c4 * 4);
        float4 bk = *(const float4 *)(kn_s + t * 68 + c4 * 4);
        float4 bq = *(const float4 *)(q_s  + t * 68 + c4 * 4);
        ak = fmaf(a.x,bk.x,fmaf(a.y,bk.y,fmaf(a.z,bk.z,fmaf(a.w,bk.w,ak))));
        aq = fmaf(a.x,bq.x,fmaf(a.y,bq.y,fmaf(a.z,bq.z,fmaf(a.w,bq.w,aq))));
    }
    scr_kk[(size_t)gb * 256 + j * 16 + t] = ak;
    scr_kq[(size_t)gb * 256 + j * 16 + t] = aq;
}

// ===== WY chunked scan v3: 256 threads, [row][t] layouts, register ph2 =====
struct __align__(16) ScanBuf {
    float kn[16 * 68], q[16 * 68];
    float v[8 * 16], g[8 * 16], ig[8 * 16];   // [row][t]
    float kk[256], kq[256];
};

__device__ __forceinline__ void wy_issue(ScanBuf *sb, int ch, int b, int r0, int tid) {
#pragma unroll
    for (int i = 0; i < 4; i++) {
        int u = tid + i * 256;            // 0..1023
        if (u < 512) {
            int t = (u & 255) >> 4, f4 = u & 15;
            size_t m = (size_t)(ch * 16 + t) * BB + b;
            if (u < 256) cp_async16(sb->kn + t * 68 + f4 * 4, scr_raw + m * NTOT + f4 * 4);
            else         cp_async16(sb->q  + t * 68 + f4 * 4, scr_raw + m * NTOT + 128 + f4 * 4);
        } else if (u < 640) {
            int w = u - 512;              // 0..127: kk(64) + kq(64) float4 units
            size_t base = (size_t)(ch * 16 + b) * 256 + (w & 63) * 4;
            if (w < 64) cp_async16(sb->kk + (w & 63) * 4, scr_kk + base);
            else        cp_async16(sb->kq + (w & 63) * 4, scr_kq + base);
        } else {
            int w = u - 640;              // 0..383: scalars v/g/ig transposed
            int arr = w >> 7, e = w & 127;
            int t = e >> 3, row = e & 7;
            size_t m = (size_t)(ch * 16 + t) * BB + b;
            float *dst = (arr == 0) ? (sb->v + row * 16 + t)
                       : (arr == 1) ? (sb->g + row * 16 + t)
                                    : (sb->ig + row * 16 + t);
            const float *src = (arr == 0) ? (scr_raw + m * NTOT + 64 + r0 + row)
                             : (arr == 1) ? (scr_raw + m * NTOT + 192 + r0 + row)
                                          : (scr_ivg + m * 64 + r0 + row);
            cp_async4(dst, src);
        }
    }
}

__global__ __launch_bounds__(256) void wy_scan_kernel(const float *__restrict__ S0,
                                                      float *__restrict__ out,
                                                      int write_sfinal) {
    __shared__ ScanBuf sb[2];
    __shared__ __align__(16) float S_s[8 * 68];
    __shared__ __align__(16) float A_s[8 * 16], Aq_s[8 * 16];   // [row][t]
    __shared__ float cp_s[8 * 17];
    __shared__ float Gs_s[16 * 8];       // [t][row]
    __shared__ float sh_out[16 * 8];     // [t][row]

    const int b = blockIdx.x, r0 = blockIdx.y * 8;
    const int tid = threadIdx.x;

    // init state: threads 0..127, one float4 each
    if (tid < 128) {
        const int rl = tid >> 4, cc = tid & 15;
        const float *sp = S0 + ((size_t)b * 64 + r0 + rl) * 64 + cc * 4;
        *(float4 *)(S_s + rl * 68 + cc * 4) = *(const float4 *)sp;
    }

    wy_issue(&sb[0], 0, b, r0, tid);
    asm volatile("cp.async.commit_group;");

    for (int ch = 0; ch < NCH; ch++) {
        const int pb = ch & 1;
        ScanBuf *B = &sb[pb];
        if (ch + 1 < NCH) {
            wy_issue(&sb[pb ^ 1], ch + 1, b, r0, tid);
            asm volatile("cp.async.commit_group;");
            asm volatile("cp.async.wait_group 1;");
        } else {
            asm volatile("cp.async.wait_group 0;");
        }
        __syncthreads();

        // ph1: 256 threads, one 64-dot each. tid<128: A; tid>=128: Aq.
        {
            const int e = tid & 127;
            const int row = e >> 4, t = e & 15;
            const float *vecs = (tid < 128) ? B->kn : B->q;
            float acc0 = 0.f;
#pragma unroll
            for (int s4 = 0; s4 < 16; s4++) {
                float4 sv = *(const float4 *)(S_s + row * 68 + s4 * 4);
                float4 kv = *(const float4 *)(vecs + t * 68 + s4 * 4);
                acc0 = fmaf(sv.x,kv.x,fmaf(sv.y,kv.y,fmaf(sv.z,kv.z,fmaf(sv.w,kv.w,acc0))));
            }
            if (tid < 128) A_s [row * 16 + t] = acc0;
            else           Aq_s[row * 16 + t] = acc0;
        }
        __syncthreads();

        // ph2: serial recursion, threads 0..7 = rows, all inputs in registers
        if (tid < 8) {
            const int row = tid;
            float a[16], vv[16], gg[16], ii[16];
#pragma unroll
            for (int s4 = 0; s4 < 4; s4++) {
                float4 t0 = *(const float4 *)(A_s   + row * 16 + s4 * 4);
                float4 t1 = *(const float4 *)(B->v  + row * 16 + s4 * 4);
                float4 t2 = *(const float4 *)(B->g  + row * 16 + s4 * 4);
                float4 t3 = *(const float4 *)(B->ig + row * 16 + s4 * 4);
                a [s4*4+0]=t0.x; a [s4*4+1]=t0.y; a [s4*4+2]=t0.z; a [s4*4+3]=t0.w;
                vv[s4*4+0]=t1.x; vv[s4*4+1]=t1.y; vv[s4*4+2]=t1.z; vv[s4*4+3]=t1.w;
                gg[s4*4+0]=t2.x; gg[s4*4+1]=t2.y; gg[s4*4+2]=t2.z; gg[s4*4+3]=t2.w;
                ii[s4*4+0]=t3.x; ii[s4*4+1]=t3.y; ii[s4*4+2]=t3.z; ii[s4*4+3]=t3.w;
            }
            float acc[16];
#pragma unroll
            for (int u = 0; u < 16; u++) acc[u] = 0.f;
            float cp[16];
            float G = 1.0f, iG = 1.0f;
#pragma unroll
            for (int t = 0; t < 16; t++) {
                float delta = vv[t] - G * (a[t] + acc[t]);
                G *= gg[t];
                iG *= ii[t];
                float ct = delta * iG;
                cp[t] = ct;
                Gs_s[t * 8 + row] = G;
#pragma unroll
                for (int u = t + 1; u < 16; u++)
                    acc[u] = fmaf(ct, B->kk[t * 16 + u], acc[u]);
            }
#pragma unroll
            for (int j = 0; j < 16; j++) cp_s[row * 17 + j] = cp[j];
        }
        __syncthreads();

        // phase B: ph3 on tid<128, ph2c on tid>=128
        if (tid < 128) {
            const int rl = tid >> 4, cc = tid & 15;
            float gl = Gs_s[15 * 8 + rl];
            float4 s0 = *(const float4 *)(S_s + rl * 68 + cc * 4);
#pragma unroll
            for (int j = 0; j < 16; j++) {
                float cj = cp_s[rl * 17 + j];
                float4 kv = *(const float4 *)(B->kn + j * 68 + cc * 4);
                s0.x = fmaf(cj, kv.x, s0.x); s0.y = fmaf(cj, kv.y, s0.y);
                s0.z = fmaf(cj, kv.z, s0.z); s0.w = fmaf(cj, kv.w, s0.w);
            }
            s0.x *= gl; s0.y *= gl; s0.z *= gl; s0.w *= gl;
            *(float4 *)(S_s + rl * 68 + cc * 4) = s0;
        } else {
            const int e = tid - 128;
            const int row = e >> 4, t = e & 15;
            float sum = Aq_s[row * 16 + t];
            for (int j = 0; j <= t; j++)
                sum = fmaf(cp_s[row * 17 + j], B->kq[j * 16 + t], sum);
            float Sq = Gs_s[t * 8 + row] * sum;
            float sg = 1.0f / (1.0f + __expf(-Sq));
            sh_out[t * 8 + row] = Sq * Sq * sg;
        }
        __syncthreads();

        // ph4: flush outputs (128 floats)
        if (tid < 128) {
            const int t = tid >> 3, r = tid & 7;
            out[(size_t)(ch * 16 + t) * (BB * NN) + b * NN + r0 + r] = sh_out[t * 8 + r];
        }
    }

    if (write_sfinal && tid < 128) {
        const int rl = tid >> 4, cc = tid & 15;
        float *sf = out + (size_t)TT * BB * NN + ((size_t)b * 64 + r0 + rl) * 64 + cc * 4;
        *(float4 *)sf = *(const float4 *)(S_s + rl * 68 + cc * 4);
    }
}

// ======================================================================
extern "C" void kernel_launch(void *const *d_in, const int *in_sizes, int n_in,
                              void *d_out, int out_size) {
    const float *x  = (const float *)d_in[0];
    const float *S0 = (const float *)d_in[1];
    const float *Wk = (const float *)d_in[2];
    const float *Wv = (const float *)d_in[3];
    const float *Wq = (const float *)d_in[4];
    const float *Wb = (const float *)d_in[5];
    const float *bb = (const float *)d_in[6];
    float *out = (float *)d_out;

    cudaFuncSetAttribute(mma_gemm_kernel, cudaFuncAttributeMaxDynamicSharedMemorySize,
                         SMEM_GEMM_TOTAL);

    copyw_kernel<<<1024, 256>>>(Wk, Wv, Wq, Wb);
    convw_kernel<<<256, 256>>>(Wk, Wv, Wq, Wb);
    convx_kernel<<<32768, 256>>>(x);

    mma_gemm_kernel<<<MROWS / 128, 128, SMEM_GEMM_TOTAL>>>();
    fb_gemm_kernel<<<dim3(MROWS / 128, 2), 256>>>(x);

    epilogue_kernel<<<4096, 256>>>(bb);
    gram_kernel<<<BB * NCH, 256>>>();

    int ws = (out_size >= TT * BB * NN + BB * NN * NN) ? 1 : 0;
    wy_scan_kernel<<<dim3(BB, 8), 256>>>(S0, out, ws);
}